// round 3
// baseline (speedup 1.0000x reference)
#include <cuda_runtime.h>
#include <cstdint>

// Problem constants
constexpr int Bb = 2;
constexpr int Tt = 2048;
constexpr int DM = 1024;
constexpr int Hh = 16;
constexpr int HD = 64;           // head dim
constexpr int MROWS = Bb * Tt;   // 4096

// Scratch buffers (no allocation allowed -> __device__ globals)
__device__ float g_Q[MROWS * DM];
__device__ float g_K[MROWS * DM];
__device__ float g_V[MROWS * DM];
__device__ float g_A[MROWS * DM];   // attention output in [b, t, h*d] layout

// ---------------------------------------------------------------------------
// Tiled NT GEMM body: C[r,c] = sum_k A[r,k] * Bm[c,k]
// M = 4096 (grid.y*128), N = 1024 (grid.x*128), K = 1024. 256 threads.
// ---------------------------------------------------------------------------
__device__ __forceinline__ void gemm_nt_body(
    const float* __restrict__ A, const float* __restrict__ Bm,
    float* __restrict__ C,
    float (*As)[132], float (*Bs)[132])
{
    const int tid = threadIdx.x;
    const int tx = tid & 15;     // 0..15 -> N micro
    const int ty = tid >> 4;     // 0..15 -> M micro
    const int row0 = blockIdx.y * 128;
    const int col0 = blockIdx.x * 128;

    float acc[8][8];
#pragma unroll
    for (int i = 0; i < 8; i++)
#pragma unroll
        for (int j = 0; j < 8; j++) acc[i][j] = 0.f;

    for (int k0 = 0; k0 < DM; k0 += 16) {
#pragma unroll
        for (int i = 0; i < 2; i++) {
            int idx = tid + i * 256;          // 0..511
            int r   = idx >> 2;               // 0..127
            int c4  = idx & 3;                // 0..3
            float4 va = *(const float4*)&A[(size_t)(row0 + r) * DM + k0 + c4 * 4];
            As[c4 * 4 + 0][r] = va.x;
            As[c4 * 4 + 1][r] = va.y;
            As[c4 * 4 + 2][r] = va.z;
            As[c4 * 4 + 3][r] = va.w;
            float4 vb = *(const float4*)&Bm[(size_t)(col0 + r) * DM + k0 + c4 * 4];
            Bs[c4 * 4 + 0][r] = vb.x;
            Bs[c4 * 4 + 1][r] = vb.y;
            Bs[c4 * 4 + 2][r] = vb.z;
            Bs[c4 * 4 + 3][r] = vb.w;
        }
        __syncthreads();
#pragma unroll
        for (int k = 0; k < 16; k++) {
            float a[8], b[8];
            float4 a0 = *(float4*)&As[k][ty * 8];
            float4 a1 = *(float4*)&As[k][ty * 8 + 4];
            float4 b0 = *(float4*)&Bs[k][tx * 8];
            float4 b1 = *(float4*)&Bs[k][tx * 8 + 4];
            a[0]=a0.x; a[1]=a0.y; a[2]=a0.z; a[3]=a0.w;
            a[4]=a1.x; a[5]=a1.y; a[6]=a1.z; a[7]=a1.w;
            b[0]=b0.x; b[1]=b0.y; b[2]=b0.z; b[3]=b0.w;
            b[4]=b1.x; b[5]=b1.y; b[6]=b1.z; b[7]=b1.w;
#pragma unroll
            for (int i = 0; i < 8; i++)
#pragma unroll
                for (int j = 0; j < 8; j++)
                    acc[i][j] += a[i] * b[j];
        }
        __syncthreads();
    }

#pragma unroll
    for (int i = 0; i < 8; i++) {
        size_t off = (size_t)(row0 + ty * 8 + i) * DM + col0 + tx * 8;
        *(float4*)&C[off]     = make_float4(acc[i][0], acc[i][1], acc[i][2], acc[i][3]);
        *(float4*)&C[off + 4] = make_float4(acc[i][4], acc[i][5], acc[i][6], acc[i][7]);
    }
}

__global__ __launch_bounds__(256) void qkv_kernel(
    const float* __restrict__ x,
    const float* __restrict__ Wq,
    const float* __restrict__ Wk,
    const float* __restrict__ Wv)
{
    __shared__ float As[16][132];
    __shared__ float Bs[16][132];
    const float* W;
    float* out;
    if (blockIdx.z == 0)      { W = Wq; out = g_Q; }
    else if (blockIdx.z == 1) { W = Wk; out = g_K; }
    else                      { W = Wv; out = g_V; }
    gemm_nt_body(x, W, out, As, Bs);
}

__global__ __launch_bounds__(256) void oproj_kernel(
    const float* __restrict__ Wo, float* __restrict__ out)
{
    __shared__ float As[16][132];
    __shared__ float Bs[16][132];
    gemm_nt_body(g_A, Wo, out, As, Bs);
}

// ---------------------------------------------------------------------------
// Flash attention (fp32, causal + key padding mask).
// grid = (T/64, B*H). block = 256 (8 warps x 8 query-rows each).
// Q/K/V read from g_Q/g_K/g_V in [b*T + t, h*64 + d] row-major layout.
// Output written to g_A in same layout (== [b, t, h*d]).
// ---------------------------------------------------------------------------
__global__ __launch_bounds__(256) void attn_kernel(const unsigned char* __restrict__ pad)
{
    __shared__ float Qs[64][68];
    __shared__ float Ks[32][68];
    __shared__ float Vs[32][68];
    __shared__ float Ps[64][36];
    __shared__ float pmadd[32];

    const int tid  = threadIdx.x;
    const int lane = tid & 31;
    const int wid  = tid >> 5;
    const int qb   = blockIdx.x;
    const int bh   = blockIdx.y;
    const int b    = bh >> 4;
    const int h    = bh & 15;
    const size_t base = (size_t)b * Tt * DM + (size_t)h * HD;

    const float scale = 0.125f;  // 1/sqrt(64)

    // Load Q tile (64 x 64), pre-scaled
    for (int i = tid; i < 64 * 16; i += 256) {
        int r = i >> 4, d4 = i & 15;
        float4 q = *(const float4*)&g_Q[base + (size_t)(qb * 64 + r) * DM + d4 * 4];
        q.x *= scale; q.y *= scale; q.z *= scale; q.w *= scale;
        *(float4*)&Qs[r][d4 * 4] = q;
    }

    float m[8], l[8];
    float2 acc[8];
#pragma unroll
    for (int r = 0; r < 8; r++) {
        m[r] = -INFINITY; l[r] = 0.f; acc[r] = make_float2(0.f, 0.f);
    }
    const int r0 = wid * 8;
    const int nkb = 2 * qb + 2;   // causal: key blocks of 32 up to query block end

    for (int kb = 0; kb < nkb; kb++) {
        __syncthreads();
        // load K/V tiles (32 x 64)
        for (int i = tid; i < 512; i += 256) {
            int key = i >> 4, d4 = i & 15;
            size_t g = base + (size_t)(kb * 32 + key) * DM + d4 * 4;
            *(float4*)&Ks[key][d4 * 4] = *(const float4*)&g_K[g];
            *(float4*)&Vs[key][d4 * 4] = *(const float4*)&g_V[g];
        }
        if (tid < 32)
            pmadd[tid] = pad[b * Tt + kb * 32 + tid] ? -INFINITY : 0.f;
        __syncthreads();

        // S = Q K^T : lane owns key = lane; 8 rows per warp
        float s[8];
#pragma unroll
        for (int r = 0; r < 8; r++) s[r] = 0.f;
#pragma unroll
        for (int d4 = 0; d4 < 16; d4++) {
            float4 k4 = *(float4*)&Ks[lane][d4 * 4];
#pragma unroll
            for (int r = 0; r < 8; r++) {
                float4 q4 = *(float4*)&Qs[r0 + r][d4 * 4];
                s[r] += q4.x * k4.x + q4.y * k4.y + q4.z * k4.z + q4.w * k4.w;
            }
        }

        const int kg = kb * 32 + lane;
        const float pmv = pmadd[lane];
#pragma unroll
        for (int r = 0; r < 8; r++) {
            int qg = qb * 64 + r0 + r;
            float sv = (kg <= qg) ? (s[r] + pmv) : -INFINITY;
            float mx = sv;
#pragma unroll
            for (int o = 16; o > 0; o >>= 1)
                mx = fmaxf(mx, __shfl_xor_sync(0xffffffffu, mx, o));
            float mnew  = fmaxf(m[r], mx);
            float p     = __expf(sv - mnew);
            float alpha = __expf(m[r] - mnew);
            float ps = p;
#pragma unroll
            for (int o = 16; o > 0; o >>= 1)
                ps += __shfl_xor_sync(0xffffffffu, ps, o);
            l[r] = l[r] * alpha + ps;
            m[r] = mnew;
            acc[r].x *= alpha;
            acc[r].y *= alpha;
            Ps[r0 + r][lane] = p;
        }
        __syncwarp();

        // O += P V : lane owns d = 2*lane, 2*lane+1
#pragma unroll
        for (int kq = 0; kq < 8; kq++) {
            float2 v0 = *(float2*)&Vs[kq * 4 + 0][2 * lane];
            float2 v1 = *(float2*)&Vs[kq * 4 + 1][2 * lane];
            float2 v2 = *(float2*)&Vs[kq * 4 + 2][2 * lane];
            float2 v3 = *(float2*)&Vs[kq * 4 + 3][2 * lane];
#pragma unroll
            for (int r = 0; r < 8; r++) {
                float4 p4 = *(float4*)&Ps[r0 + r][kq * 4];
                acc[r].x += p4.x * v0.x + p4.y * v1.x + p4.z * v2.x + p4.w * v3.x;
                acc[r].y += p4.x * v0.y + p4.y * v1.y + p4.z * v2.y + p4.w * v3.y;
            }
        }
    }

    // epilogue: normalize, write to g_A
#pragma unroll
    for (int r = 0; r < 8; r++) {
        float inv = 1.0f / l[r];
        int qg = qb * 64 + r0 + r;
        float2 o = make_float2(acc[r].x * inv, acc[r].y * inv);
        *(float2*)&g_A[base + (size_t)qg * DM + 2 * lane] = o;
    }
}

// ---------------------------------------------------------------------------
// Launch
// inputs: 0=x [2,2048,1024] f32, 1=tgt_key_padding_mask [2,2048] bool,
//         2=Wq, 3=Wk, 4=Wv, 5=Wo  (each [1024,1024] f32)
// output: [2,2048,1024] f32
// ---------------------------------------------------------------------------
extern "C" void kernel_launch(void* const* d_in, const int* in_sizes, int n_in,
                              void* d_out, int out_size)
{
    const float* x  = (const float*)d_in[0];
    const unsigned char* pad = (const unsigned char*)d_in[1];
    const float* Wq = (const float*)d_in[2];
    const float* Wk = (const float*)d_in[3];
    const float* Wv = (const float*)d_in[4];
    const float* Wo = (const float*)d_in[5];
    float* out = (float*)d_out;

    dim3 gemm_grid(DM / 128, MROWS / 128, 3);
    qkv_kernel<<<gemm_grid, 256>>>(x, Wq, Wk, Wv);

    dim3 attn_grid(Tt / 64, Bb * Hh);
    attn_kernel<<<attn_grid, 256>>>(pad);

    dim3 o_grid(DM / 128, MROWS / 128, 1);
    oproj_kernel<<<o_grid, 256>>>(Wo, out);
}

// round 5
// speedup vs baseline: 1.3874x; 1.3874x over previous
#include <cuda_runtime.h>
#include <cuda_bf16.h>
#include <cstdint>

// Problem constants
constexpr int Bb = 2;
constexpr int Tt = 2048;
constexpr int DM = 1024;
constexpr int Hh = 16;
constexpr int HD = 64;
constexpr int MROWS = Bb * Tt;   // 4096

// Scratch (no allocation allowed -> __device__ globals)
__device__ float g_Q[MROWS * DM];
__device__ float g_K[MROWS * DM];
__device__ float g_V[MROWS * DM];
__device__ float g_A[MROWS * DM];

// Split-precision bf16 operands
__device__ __nv_bfloat16 g_x_hi[MROWS * DM];
__device__ __nv_bfloat16 g_x_lo[MROWS * DM];
__device__ __nv_bfloat16 g_w_hi[4 * DM * DM];   // Wq, Wk, Wv, Wo
__device__ __nv_bfloat16 g_w_lo[4 * DM * DM];
__device__ __nv_bfloat16 g_a_hi[MROWS * DM];
__device__ __nv_bfloat16 g_a_lo[MROWS * DM];

// ---------------------------------------------------------------------------
// PTX helpers (sm_80+ only: mma.sync, ldmatrix, cp.async)
// ---------------------------------------------------------------------------
__device__ __forceinline__ uint32_t smem_u32(const void* p) {
    uint32_t a;
    asm("{ .reg .u64 t; cvta.to.shared.u64 t, %1; cvt.u32.u64 %0, t; }"
        : "=r"(a) : "l"(p));
    return a;
}

__device__ __forceinline__ void ldmat_x4(uint32_t* r, uint32_t addr) {
    asm volatile("ldmatrix.sync.aligned.m8n8.x4.shared.b16 {%0,%1,%2,%3}, [%4];"
                 : "=r"(r[0]), "=r"(r[1]), "=r"(r[2]), "=r"(r[3]) : "r"(addr));
}

__device__ __forceinline__ void mma_bf16(float* c, const uint32_t* a, const uint32_t* b) {
    asm volatile(
        "mma.sync.aligned.m16n8k16.row.col.f32.bf16.bf16.f32 "
        "{%0,%1,%2,%3}, {%4,%5,%6,%7}, {%8,%9}, {%0,%1,%2,%3};"
        : "+f"(c[0]), "+f"(c[1]), "+f"(c[2]), "+f"(c[3])
        : "r"(a[0]), "r"(a[1]), "r"(a[2]), "r"(a[3]), "r"(b[0]), "r"(b[1]));
}

__device__ __forceinline__ void cp16(uint32_t dst, const void* src) {
    asm volatile("cp.async.cg.shared.global [%0], [%1], 16;" :: "r"(dst), "l"(src));
}
__device__ __forceinline__ void cp_commit() {
    asm volatile("cp.async.commit_group;");
}
template <int N> __device__ __forceinline__ void cp_wait() {
    asm volatile("cp.async.wait_group %0;" :: "n"(N));
}

// ---------------------------------------------------------------------------
// Split fp32 -> (hi, lo) bf16
// ---------------------------------------------------------------------------
__global__ __launch_bounds__(256) void split_kernel(
    const float* __restrict__ src,
    __nv_bfloat16* __restrict__ hi,
    __nv_bfloat16* __restrict__ lo, int n4)
{
    int i = blockIdx.x * blockDim.x + threadIdx.x;
    if (i >= n4) return;
    float4 v = ((const float4*)src)[i];
    float f[4] = {v.x, v.y, v.z, v.w};
    __nv_bfloat16 h[4], l[4];
#pragma unroll
    for (int j = 0; j < 4; j++) {
        h[j] = __float2bfloat16(f[j]);
        l[j] = __float2bfloat16(f[j] - __bfloat162float(h[j]));
    }
    ((uint2*)hi)[i] = *(uint2*)h;
    ((uint2*)lo)[i] = *(uint2*)l;
}

// ---------------------------------------------------------------------------
// mma.sync split-bf16 NT GEMM: C[r,c] = sum_k A[r,k] * B[c,k]
// M = 4096 (grid.y*128), N = 1024 (grid.x*128), K = 1024.
// CTA 128x128, BK=32, 8 warps (64x32 each), cp.async double buffer.
// smem row stride 40 bf16 (80B) -> conflict-free ldmatrix.
// ---------------------------------------------------------------------------
constexpr int BK = 32;
constexpr int NCH = DM / BK;                 // 32
constexpr int RS = 40;                       // row stride in bf16 elems
constexpr uint32_t TILE_B = 128 * RS * 2;    // 10240 bytes per tensor tile
constexpr uint32_t STAGE_B = 4 * TILE_B;     // Ahi, Alo, Bhi, Blo
constexpr uint32_t GEMM_SMEM = 2 * STAGE_B;  // 81920

__global__ __launch_bounds__(256, 1)
void gemm_hmma_kernel(const __nv_bfloat16* __restrict__ Ahi,
                      const __nv_bfloat16* __restrict__ Alo,
                      const __nv_bfloat16* __restrict__ Bhi,
                      const __nv_bfloat16* __restrict__ Blo,
                      float* __restrict__ C)
{
    extern __shared__ __align__(128) char smem[];
    const uint32_t sb = smem_u32(smem);
    const int tid = threadIdx.x, lane = tid & 31, wid = tid >> 5;
    const int row0 = blockIdx.y * 128, col0 = blockIdx.x * 128;
    const int wr = wid & 1, wc = wid >> 1;       // warp tile: rows wr*64, cols wc*32
    const int m0w = wr * 64, n0w = wc * 32;

    const __nv_bfloat16* srcs[4] = {Ahi, Alo, Bhi, Blo};
    const int rb[4] = {row0, row0, col0, col0};

    float acc[4][4][4];
#pragma unroll
    for (int mi = 0; mi < 4; mi++)
#pragma unroll
        for (int ni = 0; ni < 4; ni++)
#pragma unroll
            for (int j = 0; j < 4; j++) acc[mi][ni][j] = 0.f;

    // gmem->smem loader: 2048 cp.async of 16B per chunk, 8 per thread
    auto load_chunk = [&](int c, int stage) {
        const int k0 = c * BK;
        const uint32_t stg = sb + (uint32_t)stage * STAGE_B;
#pragma unroll
        for (int j = 0; j < 8; j++) {
            int idx = tid + j * 256;             // 0..2047
            int t   = idx >> 9;                  // tensor 0..3
            int r   = (idx & 511) >> 2;          // row 0..127
            int c16 = idx & 3;                   // 16B unit 0..3
            const __nv_bfloat16* g = srcs[t] + (size_t)(rb[t] + r) * DM + k0 + c16 * 8;
            cp16(stg + (uint32_t)t * TILE_B + (uint32_t)(r * RS * 2 + c16 * 16), g);
        }
        cp_commit();
    };

    load_chunk(0, 0);

    for (int c = 0; c < NCH; c++) {
        if (c + 1 < NCH) { load_chunk(c + 1, (c + 1) & 1); cp_wait<1>(); }
        else             { cp_wait<0>(); }
        __syncthreads();

        const uint32_t stg = sb + (uint32_t)(c & 1) * STAGE_B;
        const uint32_t uAh = stg, uAl = stg + TILE_B;
        const uint32_t uBh = stg + 2 * TILE_B, uBl = stg + 3 * TILE_B;

        // ldmatrix lane-address components
        const int arow = m0w + (lane & 15);
        const int brow = n0w + (lane & 7) + ((lane >> 4) << 3);

#pragma unroll
        for (int kk = 0; kk < BK; kk += 16) {
            const int acol = kk + ((lane >> 4) << 3);
            const int bcol = kk + (((lane >> 3) & 1) << 3);
            uint32_t a_hi[4][4], a_lo[4][4], b_hi[4][2], b_lo[4][2];
#pragma unroll
            for (int mi = 0; mi < 4; mi++) {
                uint32_t off = (uint32_t)(((arow + mi * 16) * RS + acol) * 2);
                ldmat_x4(a_hi[mi], uAh + off);
                ldmat_x4(a_lo[mi], uAl + off);
            }
#pragma unroll
            for (int p = 0; p < 2; p++) {
                uint32_t off = (uint32_t)(((brow + p * 16) * RS + bcol) * 2);
                uint32_t r[4];
                ldmat_x4(r, uBh + off);
                b_hi[2 * p][0] = r[0]; b_hi[2 * p][1] = r[1];
                b_hi[2 * p + 1][0] = r[2]; b_hi[2 * p + 1][1] = r[3];
                ldmat_x4(r, uBl + off);
                b_lo[2 * p][0] = r[0]; b_lo[2 * p][1] = r[1];
                b_lo[2 * p + 1][0] = r[2]; b_lo[2 * p + 1][1] = r[3];
            }
#pragma unroll
            for (int mi = 0; mi < 4; mi++)
#pragma unroll
                for (int ni = 0; ni < 4; ni++)
                    mma_bf16(acc[mi][ni], a_hi[mi], b_hi[ni]);
#pragma unroll
            for (int mi = 0; mi < 4; mi++)
#pragma unroll
                for (int ni = 0; ni < 4; ni++)
                    mma_bf16(acc[mi][ni], a_hi[mi], b_lo[ni]);
#pragma unroll
            for (int mi = 0; mi < 4; mi++)
#pragma unroll
                for (int ni = 0; ni < 4; ni++)
                    mma_bf16(acc[mi][ni], a_lo[mi], b_hi[ni]);
        }
        __syncthreads();
    }

    // Epilogue: thread holds (groupID=lane>>2, tig=lane&3)
    const int g = lane >> 2, tg = lane & 3;
#pragma unroll
    for (int mi = 0; mi < 4; mi++) {
#pragma unroll
        for (int ni = 0; ni < 4; ni++) {
            int rgl = row0 + m0w + mi * 16 + g;
            int cgl = col0 + n0w + ni * 8 + tg * 2;
            *(float2*)&C[(size_t)rgl * DM + cgl] =
                make_float2(acc[mi][ni][0], acc[mi][ni][1]);
            *(float2*)&C[(size_t)(rgl + 8) * DM + cgl] =
                make_float2(acc[mi][ni][2], acc[mi][ni][3]);
        }
    }
}

// ---------------------------------------------------------------------------
// Flash attention (fp32, causal + key padding mask) — unchanged from R2
// ---------------------------------------------------------------------------
__global__ __launch_bounds__(256) void attn_kernel(const unsigned char* __restrict__ pad)
{
    __shared__ float Qs[64][68];
    __shared__ float Ks[32][68];
    __shared__ float Vs[32][68];
    __shared__ float Ps[64][36];
    __shared__ float pmadd[32];

    const int tid  = threadIdx.x;
    const int lane = tid & 31;
    const int wid  = tid >> 5;
    const int qb   = blockIdx.x;
    const int bh   = blockIdx.y;
    const int b    = bh >> 4;
    const int h    = bh & 15;
    const size_t base = (size_t)b * Tt * DM + (size_t)h * HD;

    const float scale = 0.125f;

    for (int i = tid; i < 64 * 16; i += 256) {
        int r = i >> 4, d4 = i & 15;
        float4 q = *(const float4*)&g_Q[base + (size_t)(qb * 64 + r) * DM + d4 * 4];
        q.x *= scale; q.y *= scale; q.z *= scale; q.w *= scale;
        *(float4*)&Qs[r][d4 * 4] = q;
    }

    float m[8], l[8];
    float2 acc[8];
#pragma unroll
    for (int r = 0; r < 8; r++) {
        m[r] = -INFINITY; l[r] = 0.f; acc[r] = make_float2(0.f, 0.f);
    }
    const int r0 = wid * 8;
    const int nkb = 2 * qb + 2;

    for (int kb = 0; kb < nkb; kb++) {
        __syncthreads();
        for (int i = tid; i < 512; i += 256) {
            int key = i >> 4, d4 = i & 15;
            size_t gaddr = base + (size_t)(kb * 32 + key) * DM + d4 * 4;
            *(float4*)&Ks[key][d4 * 4] = *(const float4*)&g_K[gaddr];
            *(float4*)&Vs[key][d4 * 4] = *(const float4*)&g_V[gaddr];
        }
        if (tid < 32)
            pmadd[tid] = pad[b * Tt + kb * 32 + tid] ? -INFINITY : 0.f;
        __syncthreads();

        float s[8];
#pragma unroll
        for (int r = 0; r < 8; r++) s[r] = 0.f;
#pragma unroll
        for (int d4 = 0; d4 < 16; d4++) {
            float4 k4 = *(float4*)&Ks[lane][d4 * 4];
#pragma unroll
            for (int r = 0; r < 8; r++) {
                float4 q4 = *(float4*)&Qs[r0 + r][d4 * 4];
                s[r] += q4.x * k4.x + q4.y * k4.y + q4.z * k4.z + q4.w * k4.w;
            }
        }

        const int kg = kb * 32 + lane;
        const float pmv = pmadd[lane];
#pragma unroll
        for (int r = 0; r < 8; r++) {
            int qg = qb * 64 + r0 + r;
            float sv = (kg <= qg) ? (s[r] + pmv) : -INFINITY;
            float mx = sv;
#pragma unroll
            for (int o = 16; o > 0; o >>= 1)
                mx = fmaxf(mx, __shfl_xor_sync(0xffffffffu, mx, o));
            float mnew  = fmaxf(m[r], mx);
            float p     = __expf(sv - mnew);
            float alpha = __expf(m[r] - mnew);
            float ps = p;
#pragma unroll
            for (int o = 16; o > 0; o >>= 1)
                ps += __shfl_xor_sync(0xffffffffu, ps, o);
            l[r] = l[r] * alpha + ps;
            m[r] = mnew;
            acc[r].x *= alpha;
            acc[r].y *= alpha;
            Ps[r0 + r][lane] = p;
        }
        __syncwarp();

#pragma unroll
        for (int kq = 0; kq < 8; kq++) {
            float2 v0 = *(float2*)&Vs[kq * 4 + 0][2 * lane];
            float2 v1 = *(float2*)&Vs[kq * 4 + 1][2 * lane];
            float2 v2 = *(float2*)&Vs[kq * 4 + 2][2 * lane];
            float2 v3 = *(float2*)&Vs[kq * 4 + 3][2 * lane];
#pragma unroll
            for (int r = 0; r < 8; r++) {
                float4 p4 = *(float4*)&Ps[r0 + r][kq * 4];
                acc[r].x += p4.x * v0.x + p4.y * v1.x + p4.z * v2.x + p4.w * v3.x;
                acc[r].y += p4.x * v0.y + p4.y * v1.y + p4.z * v2.y + p4.w * v3.y;
            }
        }
    }

#pragma unroll
    for (int r = 0; r < 8; r++) {
        float inv = 1.0f / l[r];
        int qg = qb * 64 + r0 + r;
        float2 o = make_float2(acc[r].x * inv, acc[r].y * inv);
        *(float2*)&g_A[base + (size_t)qg * DM + 2 * lane] = o;
    }
}

// ---------------------------------------------------------------------------
// Launch
// ---------------------------------------------------------------------------
extern "C" void kernel_launch(void* const* d_in, const int* in_sizes, int n_in,
                              void* d_out, int out_size)
{
    const float* x  = (const float*)d_in[0];
    const unsigned char* pad = (const unsigned char*)d_in[1];
    const float* Wq = (const float*)d_in[2];
    const float* Wk = (const float*)d_in[3];
    const float* Wv = (const float*)d_in[4];
    const float* Wo = (const float*)d_in[5];
    float* out = (float*)d_out;

    void *pxh, *pxl, *pwh, *pwl, *pah, *pal, *pQ, *pK, *pV, *pA;
    cudaGetSymbolAddress(&pxh, g_x_hi);
    cudaGetSymbolAddress(&pxl, g_x_lo);
    cudaGetSymbolAddress(&pwh, g_w_hi);
    cudaGetSymbolAddress(&pwl, g_w_lo);
    cudaGetSymbolAddress(&pah, g_a_hi);
    cudaGetSymbolAddress(&pal, g_a_lo);
    cudaGetSymbolAddress(&pQ, g_Q);
    cudaGetSymbolAddress(&pK, g_K);
    cudaGetSymbolAddress(&pV, g_V);
    cudaGetSymbolAddress(&pA, g_A);

    __nv_bfloat16* xh = (__nv_bfloat16*)pxh;
    __nv_bfloat16* xl = (__nv_bfloat16*)pxl;
    __nv_bfloat16* wh = (__nv_bfloat16*)pwh;
    __nv_bfloat16* wl = (__nv_bfloat16*)pwl;
    __nv_bfloat16* ah = (__nv_bfloat16*)pah;
    __nv_bfloat16* al = (__nv_bfloat16*)pal;

    cudaFuncSetAttribute(gemm_hmma_kernel,
                         cudaFuncAttributeMaxDynamicSharedMemorySize, GEMM_SMEM);

    const int NX4 = MROWS * DM / 4;
    const int NW4 = DM * DM / 4;
    split_kernel<<<(NX4 + 255) / 256, 256>>>(x, xh, xl, NX4);
    split_kernel<<<(NW4 + 255) / 256, 256>>>(Wq, wh + 0 * DM * DM, wl + 0 * DM * DM, NW4);
    split_kernel<<<(NW4 + 255) / 256, 256>>>(Wk, wh + 1 * DM * DM, wl + 1 * DM * DM, NW4);
    split_kernel<<<(NW4 + 255) / 256, 256>>>(Wv, wh + 2 * DM * DM, wl + 2 * DM * DM, NW4);
    split_kernel<<<(NW4 + 255) / 256, 256>>>(Wo, wh + 3 * DM * DM, wl + 3 * DM * DM, NW4);

    dim3 gg(DM / 128, MROWS / 128);
    gemm_hmma_kernel<<<gg, 256, GEMM_SMEM>>>(xh, xl, wh + 0 * DM * DM, wl + 0 * DM * DM, (float*)pQ);
    gemm_hmma_kernel<<<gg, 256, GEMM_SMEM>>>(xh, xl, wh + 1 * DM * DM, wl + 1 * DM * DM, (float*)pK);
    gemm_hmma_kernel<<<gg, 256, GEMM_SMEM>>>(xh, xl, wh + 2 * DM * DM, wl + 2 * DM * DM, (float*)pV);

    dim3 attn_grid(Tt / 64, Bb * Hh);
    attn_kernel<<<attn_grid, 256>>>(pad);

    split_kernel<<<(NX4 + 255) / 256, 256>>>((const float*)pA, ah, al, NX4);
    gemm_hmma_kernel<<<gg, 256, GEMM_SMEM>>>(ah, al, wh + 3 * DM * DM, wl + 3 * DM * DM, out);
}

// round 6
// speedup vs baseline: 1.3896x; 1.0016x over previous
#include <cuda_runtime.h>
#include <cuda_bf16.h>
#include <cstdint>

// Problem constants
constexpr int Bb = 2;
constexpr int Tt = 2048;
constexpr int DM = 1024;
constexpr int Hh = 16;
constexpr int HD = 64;
constexpr int MROWS = Bb * Tt;   // 4096

// Scratch (no allocation allowed -> __device__ globals)
__device__ float g_Q[MROWS * DM];
__device__ float g_K[MROWS * DM];
__device__ float g_V[MROWS * DM];
__device__ float g_A[MROWS * DM];

// Split-precision bf16 operands
__device__ __nv_bfloat16 g_x_hi[MROWS * DM];
__device__ __nv_bfloat16 g_x_lo[MROWS * DM];
__device__ __nv_bfloat16 g_w_hi[4 * DM * DM];   // Wq, Wk, Wv, Wo
__device__ __nv_bfloat16 g_w_lo[4 * DM * DM];
__device__ __nv_bfloat16 g_a_hi[MROWS * DM];
__device__ __nv_bfloat16 g_a_lo[MROWS * DM];

// ---------------------------------------------------------------------------
// PTX helpers (sm_80+ only: mma.sync, ldmatrix, cp.async)
// ---------------------------------------------------------------------------
__device__ __forceinline__ uint32_t smem_u32(const void* p) {
    uint32_t a;
    asm("{ .reg .u64 t; cvta.to.shared.u64 t, %1; cvt.u32.u64 %0, t; }"
        : "=r"(a) : "l"(p));
    return a;
}

__device__ __forceinline__ void ldmat_x4(uint32_t* r, uint32_t addr) {
    asm volatile("ldmatrix.sync.aligned.m8n8.x4.shared.b16 {%0,%1,%2,%3}, [%4];"
                 : "=r"(r[0]), "=r"(r[1]), "=r"(r[2]), "=r"(r[3]) : "r"(addr));
}

__device__ __forceinline__ void mma_bf16(float* c, const uint32_t* a, const uint32_t* b) {
    asm volatile(
        "mma.sync.aligned.m16n8k16.row.col.f32.bf16.bf16.f32 "
        "{%0,%1,%2,%3}, {%4,%5,%6,%7}, {%8,%9}, {%0,%1,%2,%3};"
        : "+f"(c[0]), "+f"(c[1]), "+f"(c[2]), "+f"(c[3])
        : "r"(a[0]), "r"(a[1]), "r"(a[2]), "r"(a[3]), "r"(b[0]), "r"(b[1]));
}

__device__ __forceinline__ void cp16(uint32_t dst, const void* src) {
    asm volatile("cp.async.cg.shared.global [%0], [%1], 16;" :: "r"(dst), "l"(src));
}
__device__ __forceinline__ void cp_commit() {
    asm volatile("cp.async.commit_group;");
}
template <int N> __device__ __forceinline__ void cp_wait() {
    asm volatile("cp.async.wait_group %0;" :: "n"(N));
}

// ---------------------------------------------------------------------------
// Split fp32 -> (hi, lo) bf16
// ---------------------------------------------------------------------------
__global__ __launch_bounds__(256) void split_kernel(
    const float* __restrict__ src,
    __nv_bfloat16* __restrict__ hi,
    __nv_bfloat16* __restrict__ lo, int n4)
{
    int i = blockIdx.x * blockDim.x + threadIdx.x;
    if (i >= n4) return;
    float4 v = ((const float4*)src)[i];
    float f[4] = {v.x, v.y, v.z, v.w};
    __nv_bfloat16 h[4], l[4];
#pragma unroll
    for (int j = 0; j < 4; j++) {
        h[j] = __float2bfloat16(f[j]);
        l[j] = __float2bfloat16(f[j] - __bfloat162float(h[j]));
    }
    ((uint2*)hi)[i] = *(uint2*)h;
    ((uint2*)lo)[i] = *(uint2*)l;
}

// ---------------------------------------------------------------------------
// mma.sync split-bf16 NT GEMM: C[r,c] = sum_k A[r,k] * B[c,k]
// M = 4096 (grid.y*128), N = 1024 (grid.x*128), K = 1024.
// CTA 128x128, BK=32, 8 warps (64x32 each), cp.async double buffer.
// smem row stride 40 bf16 (80B) -> conflict-free ldmatrix.
// ---------------------------------------------------------------------------
constexpr int BK = 32;
constexpr int NCH = DM / BK;                 // 32
constexpr int RS = 40;                       // row stride in bf16 elems
constexpr uint32_t TILE_B = 128 * RS * 2;    // 10240 bytes per tensor tile
constexpr uint32_t STAGE_B = 4 * TILE_B;     // Ahi, Alo, Bhi, Blo
constexpr uint32_t GEMM_SMEM = 2 * STAGE_B;  // 81920

__global__ __launch_bounds__(256, 1)
void gemm_hmma_kernel(const __nv_bfloat16* __restrict__ Ahi,
                      const __nv_bfloat16* __restrict__ Alo,
                      const __nv_bfloat16* __restrict__ Bhi,
                      const __nv_bfloat16* __restrict__ Blo,
                      float* __restrict__ C)
{
    extern __shared__ __align__(128) char smem[];
    const uint32_t sb = smem_u32(smem);
    const int tid = threadIdx.x, lane = tid & 31, wid = tid >> 5;
    const int row0 = blockIdx.y * 128, col0 = blockIdx.x * 128;
    const int wr = wid & 1, wc = wid >> 1;       // warp tile: rows wr*64, cols wc*32
    const int m0w = wr * 64, n0w = wc * 32;

    const __nv_bfloat16* srcs[4] = {Ahi, Alo, Bhi, Blo};
    const int rb[4] = {row0, row0, col0, col0};

    float acc[4][4][4];
#pragma unroll
    for (int mi = 0; mi < 4; mi++)
#pragma unroll
        for (int ni = 0; ni < 4; ni++)
#pragma unroll
            for (int j = 0; j < 4; j++) acc[mi][ni][j] = 0.f;

    // gmem->smem loader: 2048 cp.async of 16B per chunk, 8 per thread
    auto load_chunk = [&](int c, int stage) {
        const int k0 = c * BK;
        const uint32_t stg = sb + (uint32_t)stage * STAGE_B;
#pragma unroll
        for (int j = 0; j < 8; j++) {
            int idx = tid + j * 256;             // 0..2047
            int t   = idx >> 9;                  // tensor 0..3
            int r   = (idx & 511) >> 2;          // row 0..127
            int c16 = idx & 3;                   // 16B unit 0..3
            const __nv_bfloat16* g = srcs[t] + (size_t)(rb[t] + r) * DM + k0 + c16 * 8;
            cp16(stg + (uint32_t)t * TILE_B + (uint32_t)(r * RS * 2 + c16 * 16), g);
        }
        cp_commit();
    };

    load_chunk(0, 0);

    for (int c = 0; c < NCH; c++) {
        if (c + 1 < NCH) { load_chunk(c + 1, (c + 1) & 1); cp_wait<1>(); }
        else             { cp_wait<0>(); }
        __syncthreads();

        const uint32_t stg = sb + (uint32_t)(c & 1) * STAGE_B;
        const uint32_t uAh = stg, uAl = stg + TILE_B;
        const uint32_t uBh = stg + 2 * TILE_B, uBl = stg + 3 * TILE_B;

        // ldmatrix lane-address components
        const int arow = m0w + (lane & 15);
        const int brow = n0w + (lane & 7) + ((lane >> 4) << 3);

#pragma unroll
        for (int kk = 0; kk < BK; kk += 16) {
            const int acol = kk + ((lane >> 4) << 3);
            const int bcol = kk + (((lane >> 3) & 1) << 3);
            uint32_t a_hi[4][4], a_lo[4][4], b_hi[4][2], b_lo[4][2];
#pragma unroll
            for (int mi = 0; mi < 4; mi++) {
                uint32_t off = (uint32_t)(((arow + mi * 16) * RS + acol) * 2);
                ldmat_x4(a_hi[mi], uAh + off);
                ldmat_x4(a_lo[mi], uAl + off);
            }
#pragma unroll
            for (int p = 0; p < 2; p++) {
                uint32_t off = (uint32_t)(((brow + p * 16) * RS + bcol) * 2);
                uint32_t r[4];
                ldmat_x4(r, uBh + off);
                b_hi[2 * p][0] = r[0]; b_hi[2 * p][1] = r[1];
                b_hi[2 * p + 1][0] = r[2]; b_hi[2 * p + 1][1] = r[3];
                ldmat_x4(r, uBl + off);
                b_lo[2 * p][0] = r[0]; b_lo[2 * p][1] = r[1];
                b_lo[2 * p + 1][0] = r[2]; b_lo[2 * p + 1][1] = r[3];
            }
#pragma unroll
            for (int mi = 0; mi < 4; mi++)
#pragma unroll
                for (int ni = 0; ni < 4; ni++)
                    mma_bf16(acc[mi][ni], a_hi[mi], b_hi[ni]);
#pragma unroll
            for (int mi = 0; mi < 4; mi++)
#pragma unroll
                for (int ni = 0; ni < 4; ni++)
                    mma_bf16(acc[mi][ni], a_hi[mi], b_lo[ni]);
#pragma unroll
            for (int mi = 0; mi < 4; mi++)
#pragma unroll
                for (int ni = 0; ni < 4; ni++)
                    mma_bf16(acc[mi][ni], a_lo[mi], b_hi[ni]);
        }
        __syncthreads();
    }

    // Epilogue: thread holds (groupID=lane>>2, tig=lane&3)
    const int g = lane >> 2, tg = lane & 3;
#pragma unroll
    for (int mi = 0; mi < 4; mi++) {
#pragma unroll
        for (int ni = 0; ni < 4; ni++) {
            int rgl = row0 + m0w + mi * 16 + g;
            int cgl = col0 + n0w + ni * 8 + tg * 2;
            *(float2*)&C[(size_t)rgl * DM + cgl] =
                make_float2(acc[mi][ni][0], acc[mi][ni][1]);
            *(float2*)&C[(size_t)(rgl + 8) * DM + cgl] =
                make_float2(acc[mi][ni][2], acc[mi][ni][3]);
        }
    }
}

// ---------------------------------------------------------------------------
// Flash attention (fp32, causal + key padding mask) — unchanged from R2
// ---------------------------------------------------------------------------
__global__ __launch_bounds__(256) void attn_kernel(const unsigned char* __restrict__ pad)
{
    __shared__ float Qs[64][68];
    __shared__ float Ks[32][68];
    __shared__ float Vs[32][68];
    __shared__ float Ps[64][36];
    __shared__ float pmadd[32];

    const int tid  = threadIdx.x;
    const int lane = tid & 31;
    const int wid  = tid >> 5;
    const int qb   = blockIdx.x;
    const int bh   = blockIdx.y;
    const int b    = bh >> 4;
    const int h    = bh & 15;
    const size_t base = (size_t)b * Tt * DM + (size_t)h * HD;

    const float scale = 0.125f;

    for (int i = tid; i < 64 * 16; i += 256) {
        int r = i >> 4, d4 = i & 15;
        float4 q = *(const float4*)&g_Q[base + (size_t)(qb * 64 + r) * DM + d4 * 4];
        q.x *= scale; q.y *= scale; q.z *= scale; q.w *= scale;
        *(float4*)&Qs[r][d4 * 4] = q;
    }

    float m[8], l[8];
    float2 acc[8];
#pragma unroll
    for (int r = 0; r < 8; r++) {
        m[r] = -INFINITY; l[r] = 0.f; acc[r] = make_float2(0.f, 0.f);
    }
    const int r0 = wid * 8;
    const int nkb = 2 * qb + 2;

    for (int kb = 0; kb < nkb; kb++) {
        __syncthreads();
        for (int i = tid; i < 512; i += 256) {
            int key = i >> 4, d4 = i & 15;
            size_t gaddr = base + (size_t)(kb * 32 + key) * DM + d4 * 4;
            *(float4*)&Ks[key][d4 * 4] = *(const float4*)&g_K[gaddr];
            *(float4*)&Vs[key][d4 * 4] = *(const float4*)&g_V[gaddr];
        }
        if (tid < 32)
            pmadd[tid] = pad[b * Tt + kb * 32 + tid] ? -INFINITY : 0.f;
        __syncthreads();

        float s[8];
#pragma unroll
        for (int r = 0; r < 8; r++) s[r] = 0.f;
#pragma unroll
        for (int d4 = 0; d4 < 16; d4++) {
            float4 k4 = *(float4*)&Ks[lane][d4 * 4];
#pragma unroll
            for (int r = 0; r < 8; r++) {
                float4 q4 = *(float4*)&Qs[r0 + r][d4 * 4];
                s[r] += q4.x * k4.x + q4.y * k4.y + q4.z * k4.z + q4.w * k4.w;
            }
        }

        const int kg = kb * 32 + lane;
        const float pmv = pmadd[lane];
#pragma unroll
        for (int r = 0; r < 8; r++) {
            int qg = qb * 64 + r0 + r;
            float sv = (kg <= qg) ? (s[r] + pmv) : -INFINITY;
            float mx = sv;
#pragma unroll
            for (int o = 16; o > 0; o >>= 1)
                mx = fmaxf(mx, __shfl_xor_sync(0xffffffffu, mx, o));
            float mnew  = fmaxf(m[r], mx);
            float p     = __expf(sv - mnew);
            float alpha = __expf(m[r] - mnew);
            float ps = p;
#pragma unroll
            for (int o = 16; o > 0; o >>= 1)
                ps += __shfl_xor_sync(0xffffffffu, ps, o);
            l[r] = l[r] * alpha + ps;
            m[r] = mnew;
            acc[r].x *= alpha;
            acc[r].y *= alpha;
            Ps[r0 + r][lane] = p;
        }
        __syncwarp();

#pragma unroll
        for (int kq = 0; kq < 8; kq++) {
            float2 v0 = *(float2*)&Vs[kq * 4 + 0][2 * lane];
            float2 v1 = *(float2*)&Vs[kq * 4 + 1][2 * lane];
            float2 v2 = *(float2*)&Vs[kq * 4 + 2][2 * lane];
            float2 v3 = *(float2*)&Vs[kq * 4 + 3][2 * lane];
#pragma unroll
            for (int r = 0; r < 8; r++) {
                float4 p4 = *(float4*)&Ps[r0 + r][kq * 4];
                acc[r].x += p4.x * v0.x + p4.y * v1.x + p4.z * v2.x + p4.w * v3.x;
                acc[r].y += p4.x * v0.y + p4.y * v1.y + p4.z * v2.y + p4.w * v3.y;
            }
        }
    }

#pragma unroll
    for (int r = 0; r < 8; r++) {
        float inv = 1.0f / l[r];
        int qg = qb * 64 + r0 + r;
        float2 o = make_float2(acc[r].x * inv, acc[r].y * inv);
        *(float2*)&g_A[base + (size_t)qg * DM + 2 * lane] = o;
    }
}

// ---------------------------------------------------------------------------
// Launch
// ---------------------------------------------------------------------------
extern "C" void kernel_launch(void* const* d_in, const int* in_sizes, int n_in,
                              void* d_out, int out_size)
{
    const float* x  = (const float*)d_in[0];
    const unsigned char* pad = (const unsigned char*)d_in[1];
    const float* Wq = (const float*)d_in[2];
    const float* Wk = (const float*)d_in[3];
    const float* Wv = (const float*)d_in[4];
    const float* Wo = (const float*)d_in[5];
    float* out = (float*)d_out;

    void *pxh, *pxl, *pwh, *pwl, *pah, *pal, *pQ, *pK, *pV, *pA;
    cudaGetSymbolAddress(&pxh, g_x_hi);
    cudaGetSymbolAddress(&pxl, g_x_lo);
    cudaGetSymbolAddress(&pwh, g_w_hi);
    cudaGetSymbolAddress(&pwl, g_w_lo);
    cudaGetSymbolAddress(&pah, g_a_hi);
    cudaGetSymbolAddress(&pal, g_a_lo);
    cudaGetSymbolAddress(&pQ, g_Q);
    cudaGetSymbolAddress(&pK, g_K);
    cudaGetSymbolAddress(&pV, g_V);
    cudaGetSymbolAddress(&pA, g_A);

    __nv_bfloat16* xh = (__nv_bfloat16*)pxh;
    __nv_bfloat16* xl = (__nv_bfloat16*)pxl;
    __nv_bfloat16* wh = (__nv_bfloat16*)pwh;
    __nv_bfloat16* wl = (__nv_bfloat16*)pwl;
    __nv_bfloat16* ah = (__nv_bfloat16*)pah;
    __nv_bfloat16* al = (__nv_bfloat16*)pal;

    cudaFuncSetAttribute(gemm_hmma_kernel,
                         cudaFuncAttributeMaxDynamicSharedMemorySize, GEMM_SMEM);

    const int NX4 = MROWS * DM / 4;
    const int NW4 = DM * DM / 4;
    split_kernel<<<(NX4 + 255) / 256, 256>>>(x, xh, xl, NX4);
    split_kernel<<<(NW4 + 255) / 256, 256>>>(Wq, wh + 0 * DM * DM, wl + 0 * DM * DM, NW4);
    split_kernel<<<(NW4 + 255) / 256, 256>>>(Wk, wh + 1 * DM * DM, wl + 1 * DM * DM, NW4);
    split_kernel<<<(NW4 + 255) / 256, 256>>>(Wv, wh + 2 * DM * DM, wl + 2 * DM * DM, NW4);
    split_kernel<<<(NW4 + 255) / 256, 256>>>(Wo, wh + 3 * DM * DM, wl + 3 * DM * DM, NW4);

    dim3 gg(DM / 128, MROWS / 128);
    gemm_hmma_kernel<<<gg, 256, GEMM_SMEM>>>(xh, xl, wh + 0 * DM * DM, wl + 0 * DM * DM, (float*)pQ);
    gemm_hmma_kernel<<<gg, 256, GEMM_SMEM>>>(xh, xl, wh + 1 * DM * DM, wl + 1 * DM * DM, (float*)pK);
    gemm_hmma_kernel<<<gg, 256, GEMM_SMEM>>>(xh, xl, wh + 2 * DM * DM, wl + 2 * DM * DM, (float*)pV);

    dim3 attn_grid(Tt / 64, Bb * Hh);
    attn_kernel<<<attn_grid, 256>>>(pad);

    split_kernel<<<(NX4 + 255) / 256, 256>>>((const float*)pA, ah, al, NX4);
    gemm_hmma_kernel<<<gg, 256, GEMM_SMEM>>>(ah, al, wh + 3 * DM * DM, wl + 3 * DM * DM, out);
}

// round 7
// speedup vs baseline: 2.7332x; 1.9668x over previous
#include <cuda_runtime.h>
#include <cuda_bf16.h>
#include <cstdint>

// Problem constants
constexpr int Bb = 2;
constexpr int Tt = 2048;
constexpr int DM = 1024;
constexpr int Hh = 16;
constexpr int HD = 64;
constexpr int MROWS = Bb * Tt;   // 4096

// Scratch (no allocation allowed -> __device__ globals)
__device__ __nv_bfloat16 g_x_hi[MROWS * DM];
__device__ __nv_bfloat16 g_x_lo[MROWS * DM];
__device__ __nv_bfloat16 g_w_hi[4 * DM * DM];   // Wq, Wk, Wv, Wo
__device__ __nv_bfloat16 g_w_lo[4 * DM * DM];
__device__ __nv_bfloat16 g_q_hi[MROWS * DM];
__device__ __nv_bfloat16 g_q_lo[MROWS * DM];
__device__ __nv_bfloat16 g_k_hi[MROWS * DM];
__device__ __nv_bfloat16 g_k_lo[MROWS * DM];
__device__ __nv_bfloat16 g_v_hi[MROWS * DM];
__device__ __nv_bfloat16 g_v_lo[MROWS * DM];
__device__ __nv_bfloat16 g_a_hi[MROWS * DM];
__device__ __nv_bfloat16 g_a_lo[MROWS * DM];

// ---------------------------------------------------------------------------
// PTX helpers (sm_80+ only: mma.sync, ldmatrix, cp.async)
// ---------------------------------------------------------------------------
__device__ __forceinline__ uint32_t smem_u32(const void* p) {
    uint32_t a;
    asm("{ .reg .u64 t; cvta.to.shared.u64 t, %1; cvt.u32.u64 %0, t; }"
        : "=r"(a) : "l"(p));
    return a;
}

__device__ __forceinline__ void ldmat_x4(uint32_t* r, uint32_t addr) {
    asm volatile("ldmatrix.sync.aligned.m8n8.x4.shared.b16 {%0,%1,%2,%3}, [%4];"
                 : "=r"(r[0]), "=r"(r[1]), "=r"(r[2]), "=r"(r[3]) : "r"(addr));
}
__device__ __forceinline__ void ldmat_x4_t(uint32_t* r, uint32_t addr) {
    asm volatile("ldmatrix.sync.aligned.m8n8.x4.trans.shared.b16 {%0,%1,%2,%3}, [%4];"
                 : "=r"(r[0]), "=r"(r[1]), "=r"(r[2]), "=r"(r[3]) : "r"(addr));
}

__device__ __forceinline__ void mma_bf16(float* c, const uint32_t* a, const uint32_t* b) {
    asm volatile(
        "mma.sync.aligned.m16n8k16.row.col.f32.bf16.bf16.f32 "
        "{%0,%1,%2,%3}, {%4,%5,%6,%7}, {%8,%9}, {%0,%1,%2,%3};"
        : "+f"(c[0]), "+f"(c[1]), "+f"(c[2]), "+f"(c[3])
        : "r"(a[0]), "r"(a[1]), "r"(a[2]), "r"(a[3]), "r"(b[0]), "r"(b[1]));
}

__device__ __forceinline__ void cp16(uint32_t dst, const void* src) {
    asm volatile("cp.async.cg.shared.global [%0], [%1], 16;" :: "r"(dst), "l"(src));
}
__device__ __forceinline__ void cp_commit() {
    asm volatile("cp.async.commit_group;");
}
template <int N> __device__ __forceinline__ void cp_wait() {
    asm volatile("cp.async.wait_group %0;" :: "n"(N));
}

// pack two floats -> bf16x2 reg (lo in low half)
__device__ __forceinline__ uint32_t pack_bf2(float lo, float hi) {
    __nv_bfloat162 v = __floats2bfloat162_rn(lo, hi);
    return *reinterpret_cast<uint32_t*>(&v);
}

// ---------------------------------------------------------------------------
// Split fp32 -> (hi, lo) bf16
// ---------------------------------------------------------------------------
__global__ __launch_bounds__(256) void split_kernel(
    const float* __restrict__ src,
    __nv_bfloat16* __restrict__ hi,
    __nv_bfloat16* __restrict__ lo, int n4)
{
    int i = blockIdx.x * blockDim.x + threadIdx.x;
    if (i >= n4) return;
    float4 v = ((const float4*)src)[i];
    float f[4] = {v.x, v.y, v.z, v.w};
    __nv_bfloat16 h[4], l[4];
#pragma unroll
    for (int j = 0; j < 4; j++) {
        h[j] = __float2bfloat16(f[j]);
        l[j] = __float2bfloat16(f[j] - __bfloat162float(h[j]));
    }
    ((uint2*)hi)[i] = *(uint2*)h;
    ((uint2*)lo)[i] = *(uint2*)l;
}

// ---------------------------------------------------------------------------
// mma.sync split-bf16 NT GEMM: C[r,c] = sum_k A[r,k] * B[c,k]
// Output: fp32 C  OR  (outHi, outLo) bf16 pair, optionally scaled.
// ---------------------------------------------------------------------------
constexpr int BK = 32;
constexpr int NCH = DM / BK;                 // 32
constexpr int RS = 40;                       // row stride in bf16 elems
constexpr uint32_t TILE_B = 128 * RS * 2;    // 10240 bytes per tensor tile
constexpr uint32_t STAGE_B = 4 * TILE_B;
constexpr uint32_t GEMM_SMEM = 2 * STAGE_B;  // 81920

__global__ __launch_bounds__(256, 1)
void gemm_hmma_kernel(const __nv_bfloat16* __restrict__ Ahi,
                      const __nv_bfloat16* __restrict__ Alo,
                      const __nv_bfloat16* __restrict__ Bhi,
                      const __nv_bfloat16* __restrict__ Blo,
                      float* __restrict__ C,
                      __nv_bfloat16* __restrict__ outHi,
                      __nv_bfloat16* __restrict__ outLo,
                      float scale)
{
    extern __shared__ __align__(128) char smem[];
    const uint32_t sb = smem_u32(smem);
    const int tid = threadIdx.x, lane = tid & 31, wid = tid >> 5;
    const int row0 = blockIdx.y * 128, col0 = blockIdx.x * 128;
    const int wr = wid & 1, wc = wid >> 1;
    const int m0w = wr * 64, n0w = wc * 32;

    const __nv_bfloat16* srcs[4] = {Ahi, Alo, Bhi, Blo};
    const int rb[4] = {row0, row0, col0, col0};

    float acc[4][4][4];
#pragma unroll
    for (int mi = 0; mi < 4; mi++)
#pragma unroll
        for (int ni = 0; ni < 4; ni++)
#pragma unroll
            for (int j = 0; j < 4; j++) acc[mi][ni][j] = 0.f;

    auto load_chunk = [&](int c, int stage) {
        const int k0 = c * BK;
        const uint32_t stg = sb + (uint32_t)stage * STAGE_B;
#pragma unroll
        for (int j = 0; j < 8; j++) {
            int idx = tid + j * 256;
            int t   = idx >> 9;
            int r   = (idx & 511) >> 2;
            int c16 = idx & 3;
            const __nv_bfloat16* g = srcs[t] + (size_t)(rb[t] + r) * DM + k0 + c16 * 8;
            cp16(stg + (uint32_t)t * TILE_B + (uint32_t)(r * RS * 2 + c16 * 16), g);
        }
        cp_commit();
    };

    load_chunk(0, 0);

    for (int c = 0; c < NCH; c++) {
        if (c + 1 < NCH) { load_chunk(c + 1, (c + 1) & 1); cp_wait<1>(); }
        else             { cp_wait<0>(); }
        __syncthreads();

        const uint32_t stg = sb + (uint32_t)(c & 1) * STAGE_B;
        const uint32_t uAh = stg, uAl = stg + TILE_B;
        const uint32_t uBh = stg + 2 * TILE_B, uBl = stg + 3 * TILE_B;

        const int arow = m0w + (lane & 15);
        const int brow = n0w + (lane & 7) + ((lane >> 4) << 3);

#pragma unroll
        for (int kk = 0; kk < BK; kk += 16) {
            const int acol = kk + ((lane >> 4) << 3);
            const int bcol = kk + (((lane >> 3) & 1) << 3);
            uint32_t a_hi[4][4], a_lo[4][4], b_hi[4][2], b_lo[4][2];
#pragma unroll
            for (int mi = 0; mi < 4; mi++) {
                uint32_t off = (uint32_t)(((arow + mi * 16) * RS + acol) * 2);
                ldmat_x4(a_hi[mi], uAh + off);
                ldmat_x4(a_lo[mi], uAl + off);
            }
#pragma unroll
            for (int p = 0; p < 2; p++) {
                uint32_t off = (uint32_t)(((brow + p * 16) * RS + bcol) * 2);
                uint32_t r[4];
                ldmat_x4(r, uBh + off);
                b_hi[2 * p][0] = r[0]; b_hi[2 * p][1] = r[1];
                b_hi[2 * p + 1][0] = r[2]; b_hi[2 * p + 1][1] = r[3];
                ldmat_x4(r, uBl + off);
                b_lo[2 * p][0] = r[0]; b_lo[2 * p][1] = r[1];
                b_lo[2 * p + 1][0] = r[2]; b_lo[2 * p + 1][1] = r[3];
            }
#pragma unroll
            for (int mi = 0; mi < 4; mi++)
#pragma unroll
                for (int ni = 0; ni < 4; ni++)
                    mma_bf16(acc[mi][ni], a_hi[mi], b_hi[ni]);
#pragma unroll
            for (int mi = 0; mi < 4; mi++)
#pragma unroll
                for (int ni = 0; ni < 4; ni++)
                    mma_bf16(acc[mi][ni], a_hi[mi], b_lo[ni]);
#pragma unroll
            for (int mi = 0; mi < 4; mi++)
#pragma unroll
                for (int ni = 0; ni < 4; ni++)
                    mma_bf16(acc[mi][ni], a_lo[mi], b_hi[ni]);
        }
        __syncthreads();
    }

    const int g = lane >> 2, tg = lane & 3;
    if (outHi) {
#pragma unroll
        for (int mi = 0; mi < 4; mi++) {
#pragma unroll
            for (int ni = 0; ni < 4; ni++) {
                int rgl = row0 + m0w + mi * 16 + g;
                int cgl = col0 + n0w + ni * 8 + tg * 2;
#pragma unroll
                for (int half = 0; half < 2; half++) {
                    float v0 = acc[mi][ni][2 * half + 0] * scale;
                    float v1 = acc[mi][ni][2 * half + 1] * scale;
                    __nv_bfloat16 h0 = __float2bfloat16(v0);
                    __nv_bfloat16 h1 = __float2bfloat16(v1);
                    __nv_bfloat162 hv; hv.x = h0; hv.y = h1;
                    __nv_bfloat162 lv;
                    lv.x = __float2bfloat16(v0 - __bfloat162float(h0));
                    lv.y = __float2bfloat16(v1 - __bfloat162float(h1));
                    size_t off = (size_t)(rgl + 8 * half) * DM + cgl;
                    *(__nv_bfloat162*)&outHi[off] = hv;
                    *(__nv_bfloat162*)&outLo[off] = lv;
                }
            }
        }
    } else {
#pragma unroll
        for (int mi = 0; mi < 4; mi++) {
#pragma unroll
            for (int ni = 0; ni < 4; ni++) {
                int rgl = row0 + m0w + mi * 16 + g;
                int cgl = col0 + n0w + ni * 8 + tg * 2;
                *(float2*)&C[(size_t)rgl * DM + cgl] =
                    make_float2(acc[mi][ni][0], acc[mi][ni][1]);
                *(float2*)&C[(size_t)(rgl + 8) * DM + cgl] =
                    make_float2(acc[mi][ni][2], acc[mi][ni][3]);
            }
        }
    }
}

// ---------------------------------------------------------------------------
// Tensor-core flash attention (split-bf16, causal + key padding mask).
// grid = (T/128, B*H). block = 256 (8 warps x 16 query rows).
// Reads g_q_hi/lo (pre-scaled by 1/8), g_k_*, g_v_*; writes g_a_hi/lo.
// ---------------------------------------------------------------------------
constexpr int ARS = 72;                        // attn smem row stride (bf16)
constexpr uint32_t KVT = 64 * ARS * 2;         // 9216 B per tensor tile
constexpr uint32_t STG = 4 * KVT;              // 36864 B per stage
constexpr uint32_t ATTN_SMEM = 2 * STG;        // 73728 B

__global__ __launch_bounds__(256, 1)
void attn_mma_kernel(const unsigned char* __restrict__ pad)
{
    extern __shared__ __align__(128) char dsm[];
    __shared__ float pmadd[2][64];
    const uint32_t sb = smem_u32(dsm);
    const int tid = threadIdx.x, lane = tid & 31, w = tid >> 5;
    const int qb = blockIdx.x, bh = blockIdx.y, b = bh >> 4, h = bh & 15;
    const int qw0 = w * 16;           // warp's first row within the 128-q tile
    const int qt0 = qb * 128;         // tile's first query (within sequence)
    const int g = lane >> 2, tg = lane & 3;

    // ---- Load Q tile (hi/lo) into smem, then to register A-frags ----
    {
        const __nv_bfloat16* qs[2] = {g_q_hi, g_q_lo};
#pragma unroll
        for (int j = 0; j < 8; j++) {
            int idx = tid + j * 256;
            int t = idx >> 10, r = (idx & 1023) >> 3, c16 = idx & 7;
            const __nv_bfloat16* src =
                qs[t] + (size_t)(b * Tt + qt0 + r) * DM + h * HD + c16 * 8;
            cp16(sb + (uint32_t)(t * 18432 + r * 144 + c16 * 16), src);
        }
        cp_commit(); cp_wait<0>();
        __syncthreads();
    }
    uint32_t qh[4][4], ql[4][4];
    {
        int row = qw0 + (lane & 15);
#pragma unroll
        for (int kt = 0; kt < 4; kt++) {
            uint32_t off = (uint32_t)(row * 144 + kt * 32 + ((lane >> 4) << 4));
            ldmat_x4(qh[kt], sb + off);
            ldmat_x4(ql[kt], sb + 18432 + off);
        }
    }
    __syncthreads();   // Q smem free for K/V stages

    // K/V prefetch
    auto load_kv = [&](int kb2, int st) {
        const __nv_bfloat16* srcs[4] = {g_k_hi, g_k_lo, g_v_hi, g_v_lo};
#pragma unroll
        for (int j = 0; j < 8; j++) {
            int idx = tid + j * 256;
            int t = idx >> 9, r = (idx & 511) >> 3, c16 = idx & 7;
            const __nv_bfloat16* src =
                srcs[t] + (size_t)(b * Tt + kb2 * 64 + r) * DM + h * HD + c16 * 8;
            cp16(sb + (uint32_t)(st * (int)STG + t * (int)KVT + r * 144 + c16 * 16), src);
        }
        if (tid < 64)
            pmadd[st][tid] = pad[b * Tt + kb2 * 64 + tid] ? -INFINITY : 0.f;
        cp_commit();
    };

    float m0 = -INFINITY, m1 = -INFINITY, l0 = 0.f, l1 = 0.f;
    float oacc[8][4];
#pragma unroll
    for (int j = 0; j < 8; j++)
#pragma unroll
        for (int cc = 0; cc < 4; cc++) oacc[j][cc] = 0.f;

    const int nkb = 2 * qb + 2;
    load_kv(0, 0);

    for (int kb = 0; kb < nkb; kb++) {
        if (kb + 1 < nkb) { load_kv(kb + 1, (kb + 1) & 1); cp_wait<1>(); }
        else              { cp_wait<0>(); }
        __syncthreads();

        const uint32_t st = sb + (uint32_t)(kb & 1) * STG;
        const int kg0 = kb * 64;

        if (kg0 <= qt0 + qw0 + 15) {        // warp not fully masked
            // ---- S = Q K^T (3 split products) ----
            float sacc[8][4];
#pragma unroll
            for (int j = 0; j < 8; j++)
#pragma unroll
                for (int cc = 0; cc < 4; cc++) sacc[j][cc] = 0.f;

            const int brow = (lane & 7) + ((lane >> 4) << 3);
#pragma unroll
            for (int kt = 0; kt < 4; kt++) {
                uint32_t kh[8][2], kl[8][2];
                const int bcol = kt * 16 + (((lane >> 3) & 1) << 3);
#pragma unroll
                for (int p = 0; p < 4; p++) {
                    uint32_t off = (uint32_t)((brow + p * 16) * 144 + bcol * 2);
                    uint32_t r4[4];
                    ldmat_x4(r4, st + off);
                    kh[2 * p][0] = r4[0]; kh[2 * p][1] = r4[1];
                    kh[2 * p + 1][0] = r4[2]; kh[2 * p + 1][1] = r4[3];
                    ldmat_x4(r4, st + KVT + off);
                    kl[2 * p][0] = r4[0]; kl[2 * p][1] = r4[1];
                    kl[2 * p + 1][0] = r4[2]; kl[2 * p + 1][1] = r4[3];
                }
#pragma unroll
                for (int j = 0; j < 8; j++) {
                    mma_bf16(sacc[j], qh[kt], kh[j]);
                    mma_bf16(sacc[j], ql[kt], kh[j]);
                    mma_bf16(sacc[j], qh[kt], kl[j]);
                }
            }

            // ---- mask + padding ----
            const bool needmask = (kg0 + 63 > qt0 + qw0);
            const int qg0r = qt0 + qw0 + g;
            const int qg1r = qg0r + 8;
#pragma unroll
            for (int j = 0; j < 8; j++) {
                int lc = j * 8 + tg * 2;
                float pm0 = pmadd[kb & 1][lc];
                float pm1 = pmadd[kb & 1][lc + 1];
                sacc[j][0] += pm0; sacc[j][1] += pm1;
                sacc[j][2] += pm0; sacc[j][3] += pm1;
                if (needmask) {
                    int c0 = kg0 + lc;
                    if (c0     > qg0r) sacc[j][0] = -INFINITY;
                    if (c0 + 1 > qg0r) sacc[j][1] = -INFINITY;
                    if (c0     > qg1r) sacc[j][2] = -INFINITY;
                    if (c0 + 1 > qg1r) sacc[j][3] = -INFINITY;
                }
            }

            // ---- online softmax (register-resident) ----
            float mx0 = -INFINITY, mx1 = -INFINITY;
#pragma unroll
            for (int j = 0; j < 8; j++) {
                mx0 = fmaxf(mx0, fmaxf(sacc[j][0], sacc[j][1]));
                mx1 = fmaxf(mx1, fmaxf(sacc[j][2], sacc[j][3]));
            }
            mx0 = fmaxf(mx0, __shfl_xor_sync(0xffffffffu, mx0, 1));
            mx0 = fmaxf(mx0, __shfl_xor_sync(0xffffffffu, mx0, 2));
            mx1 = fmaxf(mx1, __shfl_xor_sync(0xffffffffu, mx1, 1));
            mx1 = fmaxf(mx1, __shfl_xor_sync(0xffffffffu, mx1, 2));

            float m0n = fmaxf(m0, mx0), m1n = fmaxf(m1, mx1);
            float a0 = __expf(m0 - m0n), a1 = __expf(m1 - m1n);

            float s0 = 0.f, s1 = 0.f;
#pragma unroll
            for (int j = 0; j < 8; j++) {
                sacc[j][0] = __expf(sacc[j][0] - m0n);
                sacc[j][1] = __expf(sacc[j][1] - m0n);
                sacc[j][2] = __expf(sacc[j][2] - m1n);
                sacc[j][3] = __expf(sacc[j][3] - m1n);
                s0 += sacc[j][0] + sacc[j][1];
                s1 += sacc[j][2] + sacc[j][3];
            }
            s0 += __shfl_xor_sync(0xffffffffu, s0, 1);
            s0 += __shfl_xor_sync(0xffffffffu, s0, 2);
            s1 += __shfl_xor_sync(0xffffffffu, s1, 1);
            s1 += __shfl_xor_sync(0xffffffffu, s1, 2);

            l0 = l0 * a0 + s0;  l1 = l1 * a1 + s1;
            m0 = m0n;  m1 = m1n;
#pragma unroll
            for (int j = 0; j < 8; j++) {
                oacc[j][0] *= a0; oacc[j][1] *= a0;
                oacc[j][2] *= a1; oacc[j][3] *= a1;
            }

            // ---- pack P into A-frags (hi/lo) ----
            uint32_t ph[4][4], pl[4][4];
#pragma unroll
            for (int kt = 0; kt < 4; kt++) {
#pragma unroll
                for (int half = 0; half < 2; half++) {  // half 0: S ntile 2kt; 1: 2kt+1
                    const float* s = sacc[2 * kt + half];
                    float f0 = s[0], f1 = s[1], f2 = s[2], f3 = s[3];
                    __nv_bfloat16 h0 = __float2bfloat16(f0);
                    __nv_bfloat16 h1 = __float2bfloat16(f1);
                    __nv_bfloat16 h2 = __float2bfloat16(f2);
                    __nv_bfloat16 h3 = __float2bfloat16(f3);
                    ph[kt][2 * half + 0] = pack_bf2(__bfloat162float(h0), __bfloat162float(h1));
                    ph[kt][2 * half + 1] = pack_bf2(__bfloat162float(h2), __bfloat162float(h3));
                    pl[kt][2 * half + 0] = pack_bf2(f0 - __bfloat162float(h0),
                                                    f1 - __bfloat162float(h1));
                    pl[kt][2 * half + 1] = pack_bf2(f2 - __bfloat162float(h2),
                                                    f3 - __bfloat162float(h3));
                }
            }
            // reorder: A-frag = {a0=(g,k0k1 of ntile2kt), a1=(g+8, same),
            //                    a2=(g,k of ntile2kt+1), a3=(g+8, same)}
            // built above as [2*half+0]=(g,...), [2*half+1]=(g+8,...): matches.

            // ---- O += P V (3 split products) ----
            const uint32_t vb = st + 2 * KVT;   // Vhi; Vlo at +KVT
#pragma unroll
            for (int kt = 0; kt < 4; kt++) {
                uint32_t vh[8][2], vl[8][2];
                const int vrow = kt * 16 + (lane & 15);
#pragma unroll
                for (int p = 0; p < 4; p++) {
                    uint32_t off = (uint32_t)(vrow * 144 + (p * 16 + ((lane >> 4) << 3)) * 2);
                    uint32_t r4[4];
                    ldmat_x4_t(r4, vb + off);
                    vh[2 * p][0] = r4[0]; vh[2 * p][1] = r4[1];
                    vh[2 * p + 1][0] = r4[2]; vh[2 * p + 1][1] = r4[3];
                    ldmat_x4_t(r4, vb + KVT + off);
                    vl[2 * p][0] = r4[0]; vl[2 * p][1] = r4[1];
                    vl[2 * p + 1][0] = r4[2]; vl[2 * p + 1][1] = r4[3];
                }
#pragma unroll
                for (int j = 0; j < 8; j++) {
                    mma_bf16(oacc[j], ph[kt], vh[j]);
                    mma_bf16(oacc[j], pl[kt], vh[j]);
                    mma_bf16(oacc[j], ph[kt], vl[j]);
                }
            }
        }
        __syncthreads();
    }

    // ---- epilogue: normalize, emit bf16 hi/lo ----
    float inv0 = 1.f / l0, inv1 = 1.f / l1;
    const int row0 = b * Tt + qt0 + qw0 + g;
#pragma unroll
    for (int j = 0; j < 8; j++) {
        int col = h * HD + j * 8 + tg * 2;
        float o0 = oacc[j][0] * inv0, o1 = oacc[j][1] * inv0;
        float o2 = oacc[j][2] * inv1, o3 = oacc[j][3] * inv1;
        __nv_bfloat16 h0 = __float2bfloat16(o0), h1 = __float2bfloat16(o1);
        __nv_bfloat16 h2 = __float2bfloat16(o2), h3 = __float2bfloat16(o3);
        __nv_bfloat162 hv0; hv0.x = h0; hv0.y = h1;
        __nv_bfloat162 lv0;
        lv0.x = __float2bfloat16(o0 - __bfloat162float(h0));
        lv0.y = __float2bfloat16(o1 - __bfloat162float(h1));
        __nv_bfloat162 hv1; hv1.x = h2; hv1.y = h3;
        __nv_bfloat162 lv1;
        lv1.x = __float2bfloat16(o2 - __bfloat162float(h2));
        lv1.y = __float2bfloat16(o3 - __bfloat162float(h3));
        *(__nv_bfloat162*)&g_a_hi[(size_t)row0 * DM + col] = hv0;
        *(__nv_bfloat162*)&g_a_lo[(size_t)row0 * DM + col] = lv0;
        *(__nv_bfloat162*)&g_a_hi[(size_t)(row0 + 8) * DM + col] = hv1;
        *(__nv_bfloat162*)&g_a_lo[(size_t)(row0 + 8) * DM + col] = lv1;
    }
}

// ---------------------------------------------------------------------------
// Launch
// ---------------------------------------------------------------------------
extern "C" void kernel_launch(void* const* d_in, const int* in_sizes, int n_in,
                              void* d_out, int out_size)
{
    const float* x  = (const float*)d_in[0];
    const unsigned char* pad = (const unsigned char*)d_in[1];
    const float* Wq = (const float*)d_in[2];
    const float* Wk = (const float*)d_in[3];
    const float* Wv = (const float*)d_in[4];
    const float* Wo = (const float*)d_in[5];
    float* out = (float*)d_out;

    void *pxh, *pxl, *pwh, *pwl;
    void *pqh, *pql, *pkh, *pkl, *pvh, *pvl, *pah, *pal;
    cudaGetSymbolAddress(&pxh, g_x_hi);
    cudaGetSymbolAddress(&pxl, g_x_lo);
    cudaGetSymbolAddress(&pwh, g_w_hi);
    cudaGetSymbolAddress(&pwl, g_w_lo);
    cudaGetSymbolAddress(&pqh, g_q_hi);
    cudaGetSymbolAddress(&pql, g_q_lo);
    cudaGetSymbolAddress(&pkh, g_k_hi);
    cudaGetSymbolAddress(&pkl, g_k_lo);
    cudaGetSymbolAddress(&pvh, g_v_hi);
    cudaGetSymbolAddress(&pvl, g_v_lo);
    cudaGetSymbolAddress(&pah, g_a_hi);
    cudaGetSymbolAddress(&pal, g_a_lo);

    __nv_bfloat16* xh = (__nv_bfloat16*)pxh;
    __nv_bfloat16* xl = (__nv_bfloat16*)pxl;
    __nv_bfloat16* wh = (__nv_bfloat16*)pwh;
    __nv_bfloat16* wl = (__nv_bfloat16*)pwl;

    cudaFuncSetAttribute(gemm_hmma_kernel,
                         cudaFuncAttributeMaxDynamicSharedMemorySize, GEMM_SMEM);
    cudaFuncSetAttribute(attn_mma_kernel,
                         cudaFuncAttributeMaxDynamicSharedMemorySize, ATTN_SMEM);

    const int NX4 = MROWS * DM / 4;
    const int NW4 = DM * DM / 4;
    split_kernel<<<(NX4 + 255) / 256, 256>>>(x, xh, xl, NX4);
    split_kernel<<<(NW4 + 255) / 256, 256>>>(Wq, wh + 0 * DM * DM, wl + 0 * DM * DM, NW4);
    split_kernel<<<(NW4 + 255) / 256, 256>>>(Wk, wh + 1 * DM * DM, wl + 1 * DM * DM, NW4);
    split_kernel<<<(NW4 + 255) / 256, 256>>>(Wv, wh + 2 * DM * DM, wl + 2 * DM * DM, NW4);
    split_kernel<<<(NW4 + 255) / 256, 256>>>(Wo, wh + 3 * DM * DM, wl + 3 * DM * DM, NW4);

    // Projections -> bf16 hi/lo (Q pre-scaled by 1/sqrt(HD))
    dim3 gg(DM / 128, MROWS / 128);
    gemm_hmma_kernel<<<gg, 256, GEMM_SMEM>>>(xh, xl, wh + 0 * DM * DM, wl + 0 * DM * DM,
        nullptr, (__nv_bfloat16*)pqh, (__nv_bfloat16*)pql, 0.125f);
    gemm_hmma_kernel<<<gg, 256, GEMM_SMEM>>>(xh, xl, wh + 1 * DM * DM, wl + 1 * DM * DM,
        nullptr, (__nv_bfloat16*)pkh, (__nv_bfloat16*)pkl, 1.0f);
    gemm_hmma_kernel<<<gg, 256, GEMM_SMEM>>>(xh, xl, wh + 2 * DM * DM, wl + 2 * DM * DM,
        nullptr, (__nv_bfloat16*)pvh, (__nv_bfloat16*)pvl, 1.0f);

    // Tensor-core attention -> a_hi/a_lo
    dim3 attn_grid(Tt / 128, Bb * Hh);
    attn_mma_kernel<<<attn_grid, 256, ATTN_SMEM>>>(pad);

    // O projection -> fp32 out
    gemm_hmma_kernel<<<gg, 256, GEMM_SMEM>>>(
        (__nv_bfloat16*)pah, (__nv_bfloat16*)pal, wh + 3 * DM * DM, wl + 3 * DM * DM,
        out, nullptr, nullptr, 1.0f);
}

// round 8
// speedup vs baseline: 2.7659x; 1.0120x over previous
#include <cuda_runtime.h>
#include <cuda_bf16.h>
#include <cstdint>

// Problem constants
constexpr int Bb = 2;
constexpr int Tt = 2048;
constexpr int DM = 1024;
constexpr int Hh = 16;
constexpr int HD = 64;
constexpr int MROWS = Bb * Tt;   // 4096

// Scratch (no allocation allowed -> __device__ globals)
__device__ __nv_bfloat16 g_x_hi[MROWS * DM];
__device__ __nv_bfloat16 g_x_lo[MROWS * DM];
__device__ __nv_bfloat16 g_w_hi[4 * DM * DM];   // Wq, Wk, Wv, Wo
__device__ __nv_bfloat16 g_w_lo[4 * DM * DM];
__device__ __nv_bfloat16 g_q_hi[MROWS * DM];
__device__ __nv_bfloat16 g_q_lo[MROWS * DM];
__device__ __nv_bfloat16 g_k_hi[MROWS * DM];
__device__ __nv_bfloat16 g_k_lo[MROWS * DM];
__device__ __nv_bfloat16 g_v_hi[MROWS * DM];
__device__ __nv_bfloat16 g_v_lo[MROWS * DM];
__device__ __nv_bfloat16 g_a_hi[MROWS * DM];
__device__ __nv_bfloat16 g_a_lo[MROWS * DM];

// ---------------------------------------------------------------------------
// PTX helpers (sm_80+ only: mma.sync, ldmatrix, cp.async)
// ---------------------------------------------------------------------------
__device__ __forceinline__ uint32_t smem_u32(const void* p) {
    uint32_t a;
    asm("{ .reg .u64 t; cvta.to.shared.u64 t, %1; cvt.u32.u64 %0, t; }"
        : "=r"(a) : "l"(p));
    return a;
}

__device__ __forceinline__ void ldmat_x4(uint32_t* r, uint32_t addr) {
    asm volatile("ldmatrix.sync.aligned.m8n8.x4.shared.b16 {%0,%1,%2,%3}, [%4];"
                 : "=r"(r[0]), "=r"(r[1]), "=r"(r[2]), "=r"(r[3]) : "r"(addr));
}
__device__ __forceinline__ void ldmat_x4_t(uint32_t* r, uint32_t addr) {
    asm volatile("ldmatrix.sync.aligned.m8n8.x4.trans.shared.b16 {%0,%1,%2,%3}, [%4];"
                 : "=r"(r[0]), "=r"(r[1]), "=r"(r[2]), "=r"(r[3]) : "r"(addr));
}

__device__ __forceinline__ void mma_bf16(float* c, const uint32_t* a, const uint32_t* b) {
    asm volatile(
        "mma.sync.aligned.m16n8k16.row.col.f32.bf16.bf16.f32 "
        "{%0,%1,%2,%3}, {%4,%5,%6,%7}, {%8,%9}, {%0,%1,%2,%3};"
        : "+f"(c[0]), "+f"(c[1]), "+f"(c[2]), "+f"(c[3])
        : "r"(a[0]), "r"(a[1]), "r"(a[2]), "r"(a[3]), "r"(b[0]), "r"(b[1]));
}

__device__ __forceinline__ void cp16(uint32_t dst, const void* src) {
    asm volatile("cp.async.cg.shared.global [%0], [%1], 16;" :: "r"(dst), "l"(src));
}
__device__ __forceinline__ void cp_commit() {
    asm volatile("cp.async.commit_group;");
}
template <int N> __device__ __forceinline__ void cp_wait() {
    asm volatile("cp.async.wait_group %0;" :: "n"(N));
}

__device__ __forceinline__ uint32_t pack_bf2(float lo, float hi) {
    __nv_bfloat162 v = __floats2bfloat162_rn(lo, hi);
    return *reinterpret_cast<uint32_t*>(&v);
}

// ---------------------------------------------------------------------------
// Split fp32 -> (hi, lo) bf16
// ---------------------------------------------------------------------------
__device__ __forceinline__ void split4(const float4 v, uint2& ho, uint2& lo2) {
    float f[4] = {v.x, v.y, v.z, v.w};
    __nv_bfloat16 h[4], l[4];
#pragma unroll
    for (int j = 0; j < 4; j++) {
        h[j] = __float2bfloat16(f[j]);
        l[j] = __float2bfloat16(f[j] - __bfloat162float(h[j]));
    }
    ho = *(uint2*)h;
    lo2 = *(uint2*)l;
}

__global__ __launch_bounds__(256) void split_kernel(
    const float* __restrict__ src,
    __nv_bfloat16* __restrict__ hi,
    __nv_bfloat16* __restrict__ lo, int n4)
{
    int i = blockIdx.x * blockDim.x + threadIdx.x;
    if (i >= n4) return;
    uint2 h, l;
    split4(((const float4*)src)[i], h, l);
    ((uint2*)hi)[i] = h;
    ((uint2*)lo)[i] = l;
}

// Fused split of the 4 weight matrices into g_w_hi/g_w_lo
__global__ __launch_bounds__(256) void split_w_kernel(
    const float* __restrict__ w0, const float* __restrict__ w1,
    const float* __restrict__ w2, const float* __restrict__ w3)
{
    constexpr int N4 = DM * DM / 4;   // per matrix
    int i = blockIdx.x * blockDim.x + threadIdx.x;   // 0 .. 4*N4-1
    int m = i >> 18;                   // i / N4  (N4 = 262144 = 2^18)
    int r = i & (N4 - 1);
    const float* src = (m == 0) ? w0 : (m == 1) ? w1 : (m == 2) ? w2 : w3;
    uint2 h, l;
    split4(((const float4*)src)[r], h, l);
    ((uint2*)g_w_hi)[(size_t)m * N4 + r] = h;
    ((uint2*)g_w_lo)[(size_t)m * N4 + r] = l;
}

// ---------------------------------------------------------------------------
// mma.sync split-bf16 NT GEMM body: C[r,c] = sum_k A[r,k] * B[c,k]
// CTA 128x128, BK=32, 8 warps (64x32 each), 3-stage cp.async pipeline.
// ---------------------------------------------------------------------------
constexpr int BK = 32;
constexpr int NCH = DM / BK;                 // 32
constexpr int RS = 40;                       // row stride in bf16 elems
constexpr uint32_t TILE_B = 128 * RS * 2;    // 10240 bytes per tensor tile
constexpr uint32_t STAGE_B = 4 * TILE_B;     // 40960
constexpr uint32_t GEMM_SMEM = 3 * STAGE_B;  // 122880

__device__ __forceinline__ void gemm_body(
    const __nv_bfloat16* __restrict__ Ahi,
    const __nv_bfloat16* __restrict__ Alo,
    const __nv_bfloat16* __restrict__ Bhi,
    const __nv_bfloat16* __restrict__ Blo,
    float* __restrict__ C,
    __nv_bfloat16* __restrict__ outHi,
    __nv_bfloat16* __restrict__ outLo,
    float scale, uint32_t sb, int row0, int col0)
{
    const int tid = threadIdx.x, lane = tid & 31, wid = tid >> 5;
    const int wr = wid & 1, wc = wid >> 1;
    const int m0w = wr * 64, n0w = wc * 32;

    const __nv_bfloat16* srcs[4] = {Ahi, Alo, Bhi, Blo};
    const int rb[4] = {row0, row0, col0, col0};

    float acc[4][4][4];
#pragma unroll
    for (int mi = 0; mi < 4; mi++)
#pragma unroll
        for (int ni = 0; ni < 4; ni++)
#pragma unroll
            for (int j = 0; j < 4; j++) acc[mi][ni][j] = 0.f;

    auto load_chunk = [&](int c, int stage) {
        const int k0 = c * BK;
        const uint32_t stg = sb + (uint32_t)stage * STAGE_B;
#pragma unroll
        for (int j = 0; j < 8; j++) {
            int idx = tid + j * 256;
            int t   = idx >> 9;
            int r   = (idx & 511) >> 2;
            int c16 = idx & 3;
            const __nv_bfloat16* g = srcs[t] + (size_t)(rb[t] + r) * DM + k0 + c16 * 8;
            cp16(stg + (uint32_t)t * TILE_B + (uint32_t)(r * RS * 2 + c16 * 16), g);
        }
        cp_commit();
    };

    load_chunk(0, 0);
    load_chunk(1, 1);

    for (int c = 0; c < NCH; c++) {
        if (c + 2 < NCH) { load_chunk(c + 2, (c + 2) % 3); cp_wait<2>(); }
        else if (c + 1 < NCH) { cp_wait<1>(); }
        else { cp_wait<0>(); }
        __syncthreads();

        const uint32_t stg = sb + (uint32_t)(c % 3) * STAGE_B;
        const uint32_t uAh = stg, uAl = stg + TILE_B;
        const uint32_t uBh = stg + 2 * TILE_B, uBl = stg + 3 * TILE_B;

        const int arow = m0w + (lane & 15);
        const int brow = n0w + (lane & 7) + ((lane >> 4) << 3);

#pragma unroll
        for (int kk = 0; kk < BK; kk += 16) {
            const int acol = kk + ((lane >> 4) << 3);
            const int bcol = kk + (((lane >> 3) & 1) << 3);
            uint32_t a_hi[4][4], a_lo[4][4], b_hi[4][2], b_lo[4][2];
#pragma unroll
            for (int mi = 0; mi < 4; mi++) {
                uint32_t off = (uint32_t)(((arow + mi * 16) * RS + acol) * 2);
                ldmat_x4(a_hi[mi], uAh + off);
                ldmat_x4(a_lo[mi], uAl + off);
            }
#pragma unroll
            for (int p = 0; p < 2; p++) {
                uint32_t off = (uint32_t)(((brow + p * 16) * RS + bcol) * 2);
                uint32_t r[4];
                ldmat_x4(r, uBh + off);
                b_hi[2 * p][0] = r[0]; b_hi[2 * p][1] = r[1];
                b_hi[2 * p + 1][0] = r[2]; b_hi[2 * p + 1][1] = r[3];
                ldmat_x4(r, uBl + off);
                b_lo[2 * p][0] = r[0]; b_lo[2 * p][1] = r[1];
                b_lo[2 * p + 1][0] = r[2]; b_lo[2 * p + 1][1] = r[3];
            }
#pragma unroll
            for (int mi = 0; mi < 4; mi++)
#pragma unroll
                for (int ni = 0; ni < 4; ni++)
                    mma_bf16(acc[mi][ni], a_hi[mi], b_hi[ni]);
#pragma unroll
            for (int mi = 0; mi < 4; mi++)
#pragma unroll
                for (int ni = 0; ni < 4; ni++)
                    mma_bf16(acc[mi][ni], a_hi[mi], b_lo[ni]);
#pragma unroll
            for (int mi = 0; mi < 4; mi++)
#pragma unroll
                for (int ni = 0; ni < 4; ni++)
                    mma_bf16(acc[mi][ni], a_lo[mi], b_hi[ni]);
        }
        __syncthreads();
    }

    const int g = lane >> 2, tg = lane & 3;
    if (outHi) {
#pragma unroll
        for (int mi = 0; mi < 4; mi++) {
#pragma unroll
            for (int ni = 0; ni < 4; ni++) {
                int rgl = row0 + m0w + mi * 16 + g;
                int cgl = col0 + n0w + ni * 8 + tg * 2;
#pragma unroll
                for (int half = 0; half < 2; half++) {
                    float v0 = acc[mi][ni][2 * half + 0] * scale;
                    float v1 = acc[mi][ni][2 * half + 1] * scale;
                    __nv_bfloat16 h0 = __float2bfloat16(v0);
                    __nv_bfloat16 h1 = __float2bfloat16(v1);
                    __nv_bfloat162 hv; hv.x = h0; hv.y = h1;
                    __nv_bfloat162 lv;
                    lv.x = __float2bfloat16(v0 - __bfloat162float(h0));
                    lv.y = __float2bfloat16(v1 - __bfloat162float(h1));
                    size_t off = (size_t)(rgl + 8 * half) * DM + cgl;
                    *(__nv_bfloat162*)&outHi[off] = hv;
                    *(__nv_bfloat162*)&outLo[off] = lv;
                }
            }
        }
    } else {
#pragma unroll
        for (int mi = 0; mi < 4; mi++) {
#pragma unroll
            for (int ni = 0; ni < 4; ni++) {
                int rgl = row0 + m0w + mi * 16 + g;
                int cgl = col0 + n0w + ni * 8 + tg * 2;
                *(float2*)&C[(size_t)rgl * DM + cgl] =
                    make_float2(acc[mi][ni][0], acc[mi][ni][1]);
                *(float2*)&C[(size_t)(rgl + 8) * DM + cgl] =
                    make_float2(acc[mi][ni][2], acc[mi][ni][3]);
            }
        }
    }
}

// Fused QKV: grid (8, 32, 3)
__global__ __launch_bounds__(256, 1)
void qkv_fused_kernel()
{
    extern __shared__ __align__(128) char smem[];
    const uint32_t sb = smem_u32(smem);
    const int z = blockIdx.z;
    const __nv_bfloat16* wh = g_w_hi + (size_t)z * DM * DM;
    const __nv_bfloat16* wl = g_w_lo + (size_t)z * DM * DM;
    __nv_bfloat16* oh = (z == 0) ? g_q_hi : (z == 1) ? g_k_hi : g_v_hi;
    __nv_bfloat16* ol = (z == 0) ? g_q_lo : (z == 1) ? g_k_lo : g_v_lo;
    float scale = (z == 0) ? 0.125f : 1.0f;
    gemm_body(g_x_hi, g_x_lo, wh, wl, nullptr, oh, ol, scale, sb,
              blockIdx.y * 128, blockIdx.x * 128);
}

// O projection: grid (8, 32)
__global__ __launch_bounds__(256, 1)
void oproj_kernel(float* __restrict__ out)
{
    extern __shared__ __align__(128) char smem[];
    const uint32_t sb = smem_u32(smem);
    gemm_body(g_a_hi, g_a_lo, g_w_hi + (size_t)3 * DM * DM, g_w_lo + (size_t)3 * DM * DM,
              out, nullptr, nullptr, 1.0f, sb, blockIdx.y * 128, blockIdx.x * 128);
}

// ---------------------------------------------------------------------------
// Tensor-core flash attention (split-bf16, causal + key padding mask).
// grid = (T/128, B*H). block = 256 (8 warps x 16 query rows).
// qb REVERSED so heavy tiles are scheduled first.
// ---------------------------------------------------------------------------
constexpr int ARS = 72;
constexpr uint32_t KVT = 64 * ARS * 2;         // 9216 B per tensor tile
constexpr uint32_t STG = 4 * KVT;              // 36864 B per stage
constexpr uint32_t ATTN_SMEM = 2 * STG;        // 73728 B

__global__ __launch_bounds__(256, 1)
void attn_mma_kernel(const unsigned char* __restrict__ pad)
{
    extern __shared__ __align__(128) char dsm[];
    __shared__ float pmadd[2][64];
    const uint32_t sb = smem_u32(dsm);
    const int tid = threadIdx.x, lane = tid & 31, w = tid >> 5;
    const int qb = gridDim.x - 1 - blockIdx.x;   // heavy tiles first
    const int bh = blockIdx.y, b = bh >> 4, h = bh & 15;
    const int qw0 = w * 16;
    const int qt0 = qb * 128;
    const int g = lane >> 2, tg = lane & 3;

    // ---- Load Q tile (hi/lo) into smem, then to register A-frags ----
    {
        const __nv_bfloat16* qs[2] = {g_q_hi, g_q_lo};
#pragma unroll
        for (int j = 0; j < 8; j++) {
            int idx = tid + j * 256;
            int t = idx >> 10, r = (idx & 1023) >> 3, c16 = idx & 7;
            const __nv_bfloat16* src =
                qs[t] + (size_t)(b * Tt + qt0 + r) * DM + h * HD + c16 * 8;
            cp16(sb + (uint32_t)(t * 18432 + r * 144 + c16 * 16), src);
        }
        cp_commit(); cp_wait<0>();
        __syncthreads();
    }
    uint32_t qh[4][4], ql[4][4];
    {
        int row = qw0 + (lane & 15);
#pragma unroll
        for (int kt = 0; kt < 4; kt++) {
            uint32_t off = (uint32_t)(row * 144 + kt * 32 + ((lane >> 4) << 4));
            ldmat_x4(qh[kt], sb + off);
            ldmat_x4(ql[kt], sb + 18432 + off);
        }
    }
    __syncthreads();

    auto load_kv = [&](int kb2, int st) {
        const __nv_bfloat16* srcs[4] = {g_k_hi, g_k_lo, g_v_hi, g_v_lo};
#pragma unroll
        for (int j = 0; j < 8; j++) {
            int idx = tid + j * 256;
            int t = idx >> 9, r = (idx & 511) >> 3, c16 = idx & 7;
            const __nv_bfloat16* src =
                srcs[t] + (size_t)(b * Tt + kb2 * 64 + r) * DM + h * HD + c16 * 8;
            cp16(sb + (uint32_t)(st * (int)STG + t * (int)KVT + r * 144 + c16 * 16), src);
        }
        if (tid < 64)
            pmadd[st][tid] = pad[b * Tt + kb2 * 64 + tid] ? -INFINITY : 0.f;
        cp_commit();
    };

    float m0 = -INFINITY, m1 = -INFINITY, l0 = 0.f, l1 = 0.f;
    float oacc[8][4];
#pragma unroll
    for (int j = 0; j < 8; j++)
#pragma unroll
        for (int cc = 0; cc < 4; cc++) oacc[j][cc] = 0.f;

    const int nkb = 2 * qb + 2;
    load_kv(0, 0);

    for (int kb = 0; kb < nkb; kb++) {
        if (kb + 1 < nkb) { load_kv(kb + 1, (kb + 1) & 1); cp_wait<1>(); }
        else              { cp_wait<0>(); }
        __syncthreads();

        const uint32_t st = sb + (uint32_t)(kb & 1) * STG;
        const int kg0 = kb * 64;

        if (kg0 <= qt0 + qw0 + 15) {
            float sacc[8][4];
#pragma unroll
            for (int j = 0; j < 8; j++)
#pragma unroll
                for (int cc = 0; cc < 4; cc++) sacc[j][cc] = 0.f;

            const int brow = (lane & 7) + ((lane >> 4) << 3);
#pragma unroll
            for (int kt = 0; kt < 4; kt++) {
                uint32_t kh[8][2], kl[8][2];
                const int bcol = kt * 16 + (((lane >> 3) & 1) << 3);
#pragma unroll
                for (int p = 0; p < 4; p++) {
                    uint32_t off = (uint32_t)((brow + p * 16) * 144 + bcol * 2);
                    uint32_t r4[4];
                    ldmat_x4(r4, st + off);
                    kh[2 * p][0] = r4[0]; kh[2 * p][1] = r4[1];
                    kh[2 * p + 1][0] = r4[2]; kh[2 * p + 1][1] = r4[3];
                    ldmat_x4(r4, st + KVT + off);
                    kl[2 * p][0] = r4[0]; kl[2 * p][1] = r4[1];
                    kl[2 * p + 1][0] = r4[2]; kl[2 * p + 1][1] = r4[3];
                }
#pragma unroll
                for (int j = 0; j < 8; j++) {
                    mma_bf16(sacc[j], qh[kt], kh[j]);
                    mma_bf16(sacc[j], ql[kt], kh[j]);
                    mma_bf16(sacc[j], qh[kt], kl[j]);
                }
            }

            const bool needmask = (kg0 + 63 > qt0 + qw0);
            const int qg0r = qt0 + qw0 + g;
            const int qg1r = qg0r + 8;
#pragma unroll
            for (int j = 0; j < 8; j++) {
                int lc = j * 8 + tg * 2;
                float pm0 = pmadd[kb & 1][lc];
                float pm1 = pmadd[kb & 1][lc + 1];
                sacc[j][0] += pm0; sacc[j][1] += pm1;
                sacc[j][2] += pm0; sacc[j][3] += pm1;
                if (needmask) {
                    int c0 = kg0 + lc;
                    if (c0     > qg0r) sacc[j][0] = -INFINITY;
                    if (c0 + 1 > qg0r) sacc[j][1] = -INFINITY;
                    if (c0     > qg1r) sacc[j][2] = -INFINITY;
                    if (c0 + 1 > qg1r) sacc[j][3] = -INFINITY;
                }
            }

            float mx0 = -INFINITY, mx1 = -INFINITY;
#pragma unroll
            for (int j = 0; j < 8; j++) {
                mx0 = fmaxf(mx0, fmaxf(sacc[j][0], sacc[j][1]));
                mx1 = fmaxf(mx1, fmaxf(sacc[j][2], sacc[j][3]));
            }
            mx0 = fmaxf(mx0, __shfl_xor_sync(0xffffffffu, mx0, 1));
            mx0 = fmaxf(mx0, __shfl_xor_sync(0xffffffffu, mx0, 2));
            mx1 = fmaxf(mx1, __shfl_xor_sync(0xffffffffu, mx1, 1));
            mx1 = fmaxf(mx1, __shfl_xor_sync(0xffffffffu, mx1, 2));

            float m0n = fmaxf(m0, mx0), m1n = fmaxf(m1, mx1);
            float a0 = __expf(m0 - m0n), a1 = __expf(m1 - m1n);

            float s0 = 0.f, s1 = 0.f;
#pragma unroll
            for (int j = 0; j < 8; j++) {
                sacc[j][0] = __expf(sacc[j][0] - m0n);
                sacc[j][1] = __expf(sacc[j][1] - m0n);
                sacc[j][2] = __expf(sacc[j][2] - m1n);
                sacc[j][3] = __expf(sacc[j][3] - m1n);
                s0 += sacc[j][0] + sacc[j][1];
                s1 += sacc[j][2] + sacc[j][3];
            }
            s0 += __shfl_xor_sync(0xffffffffu, s0, 1);
            s0 += __shfl_xor_sync(0xffffffffu, s0, 2);
            s1 += __shfl_xor_sync(0xffffffffu, s1, 1);
            s1 += __shfl_xor_sync(0xffffffffu, s1, 2);

            l0 = l0 * a0 + s0;  l1 = l1 * a1 + s1;
            m0 = m0n;  m1 = m1n;
#pragma unroll
            for (int j = 0; j < 8; j++) {
                oacc[j][0] *= a0; oacc[j][1] *= a0;
                oacc[j][2] *= a1; oacc[j][3] *= a1;
            }

            uint32_t ph[4][4], pl[4][4];
#pragma unroll
            for (int kt = 0; kt < 4; kt++) {
#pragma unroll
                for (int half = 0; half < 2; half++) {
                    const float* s = sacc[2 * kt + half];
                    float f0 = s[0], f1 = s[1], f2 = s[2], f3 = s[3];
                    __nv_bfloat16 h0 = __float2bfloat16(f0);
                    __nv_bfloat16 h1 = __float2bfloat16(f1);
                    __nv_bfloat16 h2 = __float2bfloat16(f2);
                    __nv_bfloat16 h3 = __float2bfloat16(f3);
                    ph[kt][2 * half + 0] = pack_bf2(__bfloat162float(h0), __bfloat162float(h1));
                    ph[kt][2 * half + 1] = pack_bf2(__bfloat162float(h2), __bfloat162float(h3));
                    pl[kt][2 * half + 0] = pack_bf2(f0 - __bfloat162float(h0),
                                                    f1 - __bfloat162float(h1));
                    pl[kt][2 * half + 1] = pack_bf2(f2 - __bfloat162float(h2),
                                                    f3 - __bfloat162float(h3));
                }
            }

            const uint32_t vb = st + 2 * KVT;
#pragma unroll
            for (int kt = 0; kt < 4; kt++) {
                uint32_t vh[8][2], vl[8][2];
                const int vrow = kt * 16 + (lane & 15);
#pragma unroll
                for (int p = 0; p < 4; p++) {
                    uint32_t off = (uint32_t)(vrow * 144 + (p * 16 + ((lane >> 4) << 3)) * 2);
                    uint32_t r4[4];
                    ldmat_x4_t(r4, vb + off);
                    vh[2 * p][0] = r4[0]; vh[2 * p][1] = r4[1];
                    vh[2 * p + 1][0] = r4[2]; vh[2 * p + 1][1] = r4[3];
                    ldmat_x4_t(r4, vb + KVT + off);
                    vl[2 * p][0] = r4[0]; vl[2 * p][1] = r4[1];
                    vl[2 * p + 1][0] = r4[2]; vl[2 * p + 1][1] = r4[3];
                }
#pragma unroll
                for (int j = 0; j < 8; j++) {
                    mma_bf16(oacc[j], ph[kt], vh[j]);
                    mma_bf16(oacc[j], pl[kt], vh[j]);
                    mma_bf16(oacc[j], ph[kt], vl[j]);
                }
            }
        }
        __syncthreads();
    }

    float inv0 = 1.f / l0, inv1 = 1.f / l1;
    const int row0 = b * Tt + qt0 + qw0 + g;
#pragma unroll
    for (int j = 0; j < 8; j++) {
        int col = h * HD + j * 8 + tg * 2;
        float o0 = oacc[j][0] * inv0, o1 = oacc[j][1] * inv0;
        float o2 = oacc[j][2] * inv1, o3 = oacc[j][3] * inv1;
        __nv_bfloat16 h0 = __float2bfloat16(o0), h1 = __float2bfloat16(o1);
        __nv_bfloat16 h2 = __float2bfloat16(o2), h3 = __float2bfloat16(o3);
        __nv_bfloat162 hv0; hv0.x = h0; hv0.y = h1;
        __nv_bfloat162 lv0;
        lv0.x = __float2bfloat16(o0 - __bfloat162float(h0));
        lv0.y = __float2bfloat16(o1 - __bfloat162float(h1));
        __nv_bfloat162 hv1; hv1.x = h2; hv1.y = h3;
        __nv_bfloat162 lv1;
        lv1.x = __float2bfloat16(o2 - __bfloat162float(h2));
        lv1.y = __float2bfloat16(o3 - __bfloat162float(h3));
        *(__nv_bfloat162*)&g_a_hi[(size_t)row0 * DM + col] = hv0;
        *(__nv_bfloat162*)&g_a_lo[(size_t)row0 * DM + col] = lv0;
        *(__nv_bfloat162*)&g_a_hi[(size_t)(row0 + 8) * DM + col] = hv1;
        *(__nv_bfloat162*)&g_a_lo[(size_t)(row0 + 8) * DM + col] = lv1;
    }
}

// ---------------------------------------------------------------------------
// Launch
// ---------------------------------------------------------------------------
extern "C" void kernel_launch(void* const* d_in, const int* in_sizes, int n_in,
                              void* d_out, int out_size)
{
    const float* x  = (const float*)d_in[0];
    const unsigned char* pad = (const unsigned char*)d_in[1];
    const float* Wq = (const float*)d_in[2];
    const float* Wk = (const float*)d_in[3];
    const float* Wv = (const float*)d_in[4];
    const float* Wo = (const float*)d_in[5];
    float* out = (float*)d_out;

    void *pxh, *pxl;
    cudaGetSymbolAddress(&pxh, g_x_hi);
    cudaGetSymbolAddress(&pxl, g_x_lo);

    cudaFuncSetAttribute(qkv_fused_kernel,
                         cudaFuncAttributeMaxDynamicSharedMemorySize, GEMM_SMEM);
    cudaFuncSetAttribute(oproj_kernel,
                         cudaFuncAttributeMaxDynamicSharedMemorySize, GEMM_SMEM);
    cudaFuncSetAttribute(attn_mma_kernel,
                         cudaFuncAttributeMaxDynamicSharedMemorySize, ATTN_SMEM);

    const int NX4 = MROWS * DM / 4;
    split_kernel<<<(NX4 + 255) / 256, 256>>>(x, (__nv_bfloat16*)pxh, (__nv_bfloat16*)pxl, NX4);
    split_w_kernel<<<4 * (DM * DM / 4) / 256, 256>>>(Wq, Wk, Wv, Wo);

    dim3 gg(DM / 128, MROWS / 128, 3);
    qkv_fused_kernel<<<gg, 256, GEMM_SMEM>>>();

    dim3 attn_grid(Tt / 128, Bb * Hh);
    attn_mma_kernel<<<attn_grid, 256, ATTN_SMEM>>>(pad);

    dim3 og(DM / 128, MROWS / 128);
    oproj_kernel<<<og, 256, GEMM_SMEM>>>(out);
}

// round 9
// speedup vs baseline: 2.7662x; 1.0001x over previous
#include <cuda_runtime.h>
#include <cuda_bf16.h>
#include <cstdint>

// Problem constants
constexpr int Bb = 2;
constexpr int Tt = 2048;
constexpr int DM = 1024;
constexpr int Hh = 16;
constexpr int HD = 64;
constexpr int MROWS = Bb * Tt;   // 4096

// Scratch (no allocation allowed -> __device__ globals)
__device__ __nv_bfloat16 g_x_hi[MROWS * DM];
__device__ __nv_bfloat16 g_x_lo[MROWS * DM];
__device__ __nv_bfloat16 g_w_hi[4 * DM * DM];   // Wq, Wk, Wv, Wo
__device__ __nv_bfloat16 g_w_lo[4 * DM * DM];
__device__ __nv_bfloat16 g_q_hi[MROWS * DM];
__device__ __nv_bfloat16 g_q_lo[MROWS * DM];
__device__ __nv_bfloat16 g_k_hi[MROWS * DM];
__device__ __nv_bfloat16 g_k_lo[MROWS * DM];
__device__ __nv_bfloat16 g_v_hi[MROWS * DM];
__device__ __nv_bfloat16 g_v_lo[MROWS * DM];
__device__ __nv_bfloat16 g_a_hi[MROWS * DM];
__device__ __nv_bfloat16 g_a_lo[MROWS * DM];

// ---------------------------------------------------------------------------
// PTX helpers
// ---------------------------------------------------------------------------
__device__ __forceinline__ uint32_t smem_u32(const void* p) {
    uint32_t a;
    asm("{ .reg .u64 t; cvta.to.shared.u64 t, %1; cvt.u32.u64 %0, t; }"
        : "=r"(a) : "l"(p));
    return a;
}

__device__ __forceinline__ void ldmat_x4(uint32_t* r, uint32_t addr) {
    asm volatile("ldmatrix.sync.aligned.m8n8.x4.shared.b16 {%0,%1,%2,%3}, [%4];"
                 : "=r"(r[0]), "=r"(r[1]), "=r"(r[2]), "=r"(r[3]) : "r"(addr));
}
__device__ __forceinline__ void ldmat_x4_t(uint32_t* r, uint32_t addr) {
    asm volatile("ldmatrix.sync.aligned.m8n8.x4.trans.shared.b16 {%0,%1,%2,%3}, [%4];"
                 : "=r"(r[0]), "=r"(r[1]), "=r"(r[2]), "=r"(r[3]) : "r"(addr));
}

__device__ __forceinline__ void mma_bf16(float* c, const uint32_t* a, const uint32_t* b) {
    asm volatile(
        "mma.sync.aligned.m16n8k16.row.col.f32.bf16.bf16.f32 "
        "{%0,%1,%2,%3}, {%4,%5,%6,%7}, {%8,%9}, {%0,%1,%2,%3};"
        : "+f"(c[0]), "+f"(c[1]), "+f"(c[2]), "+f"(c[3])
        : "r"(a[0]), "r"(a[1]), "r"(a[2]), "r"(a[3]), "r"(b[0]), "r"(b[1]));
}

__device__ __forceinline__ void cp16(uint32_t dst, const void* src) {
    asm volatile("cp.async.cg.shared.global [%0], [%1], 16;" :: "r"(dst), "l"(src));
}
__device__ __forceinline__ void cp_commit() {
    asm volatile("cp.async.commit_group;");
}
template <int N> __device__ __forceinline__ void cp_wait() {
    asm volatile("cp.async.wait_group %0;" :: "n"(N));
}

__device__ __forceinline__ uint32_t pack_bf2(float lo, float hi) {
    __nv_bfloat162 v = __floats2bfloat162_rn(lo, hi);
    return *reinterpret_cast<uint32_t*>(&v);
}

// ---------------------------------------------------------------------------
// Split fp32 -> (hi, lo) bf16
// ---------------------------------------------------------------------------
__device__ __forceinline__ void split4(const float4 v, uint2& ho, uint2& lo2) {
    float f[4] = {v.x, v.y, v.z, v.w};
    __nv_bfloat16 h[4], l[4];
#pragma unroll
    for (int j = 0; j < 4; j++) {
        h[j] = __float2bfloat16(f[j]);
        l[j] = __float2bfloat16(f[j] - __bfloat162float(h[j]));
    }
    ho = *(uint2*)h;
    lo2 = *(uint2*)l;
}

__global__ __launch_bounds__(256) void split_kernel(
    const float* __restrict__ src,
    __nv_bfloat16* __restrict__ hi,
    __nv_bfloat16* __restrict__ lo, int n4)
{
    int i = blockIdx.x * blockDim.x + threadIdx.x;
    if (i >= n4) return;
    uint2 h, l;
    split4(((const float4*)src)[i], h, l);
    ((uint2*)hi)[i] = h;
    ((uint2*)lo)[i] = l;
}

__global__ __launch_bounds__(256) void split_w_kernel(
    const float* __restrict__ w0, const float* __restrict__ w1,
    const float* __restrict__ w2, const float* __restrict__ w3)
{
    constexpr int N4 = DM * DM / 4;
    int i = blockIdx.x * blockDim.x + threadIdx.x;
    int m = i >> 18;
    int r = i & (N4 - 1);
    const float* src = (m == 0) ? w0 : (m == 1) ? w1 : (m == 2) ? w2 : w3;
    uint2 h, l;
    split4(((const float4*)src)[r], h, l);
    ((uint2*)g_w_hi)[(size_t)m * N4 + r] = h;
    ((uint2*)g_w_lo)[(size_t)m * N4 + r] = l;
}

// ---------------------------------------------------------------------------
// mma.sync split-bf16 NT GEMM body, 512 threads: 16 warps x 32x32 tiles.
// CTA 128x128, BK=32, 3-stage cp.async pipeline.
// ---------------------------------------------------------------------------
constexpr int BK = 32;
constexpr int NCH = DM / BK;                 // 32
constexpr int RS = 40;                       // row stride in bf16 elems
constexpr uint32_t TILE_B = 128 * RS * 2;    // 10240
constexpr uint32_t STAGE_B = 4 * TILE_B;     // 40960
constexpr uint32_t GEMM_SMEM = 3 * STAGE_B;  // 122880

__device__ __forceinline__ void gemm_body(
    const __nv_bfloat16* __restrict__ Ahi,
    const __nv_bfloat16* __restrict__ Alo,
    const __nv_bfloat16* __restrict__ Bhi,
    const __nv_bfloat16* __restrict__ Blo,
    float* __restrict__ C,
    __nv_bfloat16* __restrict__ outHi,
    __nv_bfloat16* __restrict__ outLo,
    float scale, uint32_t sb, int row0, int col0)
{
    const int tid = threadIdx.x, lane = tid & 31, wid = tid >> 5;
    const int wr = wid & 3, wc = wid >> 2;          // 4x4 warp grid
    const int m0w = wr * 32, n0w = wc * 32;

    const __nv_bfloat16* srcs[4] = {Ahi, Alo, Bhi, Blo};
    const int rb[4] = {row0, row0, col0, col0};

    float acc[2][4][4];
#pragma unroll
    for (int mi = 0; mi < 2; mi++)
#pragma unroll
        for (int ni = 0; ni < 4; ni++)
#pragma unroll
            for (int j = 0; j < 4; j++) acc[mi][ni][j] = 0.f;

    auto load_chunk = [&](int c, int stage) {
        const int k0 = c * BK;
        const uint32_t stg = sb + (uint32_t)stage * STAGE_B;
#pragma unroll
        for (int j = 0; j < 4; j++) {
            int idx = tid + j * 512;
            int t   = idx >> 9;
            int r   = (idx & 511) >> 2;
            int c16 = idx & 3;
            const __nv_bfloat16* g = srcs[t] + (size_t)(rb[t] + r) * DM + k0 + c16 * 8;
            cp16(stg + (uint32_t)t * TILE_B + (uint32_t)(r * RS * 2 + c16 * 16), g);
        }
        cp_commit();
    };

    load_chunk(0, 0);
    load_chunk(1, 1);

    for (int c = 0; c < NCH; c++) {
        if (c + 2 < NCH) { load_chunk(c + 2, (c + 2) % 3); cp_wait<2>(); }
        else if (c + 1 < NCH) { cp_wait<1>(); }
        else { cp_wait<0>(); }
        __syncthreads();

        const uint32_t stg = sb + (uint32_t)(c % 3) * STAGE_B;
        const uint32_t uAh = stg, uAl = stg + TILE_B;
        const uint32_t uBh = stg + 2 * TILE_B, uBl = stg + 3 * TILE_B;

        const int arow = m0w + (lane & 15);
        const int brow = n0w + (lane & 7) + ((lane >> 4) << 3);

#pragma unroll
        for (int kk = 0; kk < BK; kk += 16) {
            const int acol = kk + ((lane >> 4) << 3);
            const int bcol = kk + (((lane >> 3) & 1) << 3);
            uint32_t a_hi[2][4], a_lo[2][4], b_hi[4][2], b_lo[4][2];
#pragma unroll
            for (int mi = 0; mi < 2; mi++) {
                uint32_t off = (uint32_t)(((arow + mi * 16) * RS + acol) * 2);
                ldmat_x4(a_hi[mi], uAh + off);
                ldmat_x4(a_lo[mi], uAl + off);
            }
#pragma unroll
            for (int p = 0; p < 2; p++) {
                uint32_t off = (uint32_t)(((brow + p * 16) * RS + bcol) * 2);
                uint32_t r[4];
                ldmat_x4(r, uBh + off);
                b_hi[2 * p][0] = r[0]; b_hi[2 * p][1] = r[1];
                b_hi[2 * p + 1][0] = r[2]; b_hi[2 * p + 1][1] = r[3];
                ldmat_x4(r, uBl + off);
                b_lo[2 * p][0] = r[0]; b_lo[2 * p][1] = r[1];
                b_lo[2 * p + 1][0] = r[2]; b_lo[2 * p + 1][1] = r[3];
            }
#pragma unroll
            for (int mi = 0; mi < 2; mi++)
#pragma unroll
                for (int ni = 0; ni < 4; ni++)
                    mma_bf16(acc[mi][ni], a_hi[mi], b_hi[ni]);
#pragma unroll
            for (int mi = 0; mi < 2; mi++)
#pragma unroll
                for (int ni = 0; ni < 4; ni++)
                    mma_bf16(acc[mi][ni], a_hi[mi], b_lo[ni]);
#pragma unroll
            for (int mi = 0; mi < 2; mi++)
#pragma unroll
                for (int ni = 0; ni < 4; ni++)
                    mma_bf16(acc[mi][ni], a_lo[mi], b_hi[ni]);
        }
        __syncthreads();
    }

    const int g = lane >> 2, tg = lane & 3;
    if (outHi) {
#pragma unroll
        for (int mi = 0; mi < 2; mi++) {
#pragma unroll
            for (int ni = 0; ni < 4; ni++) {
                int rgl = row0 + m0w + mi * 16 + g;
                int cgl = col0 + n0w + ni * 8 + tg * 2;
#pragma unroll
                for (int half = 0; half < 2; half++) {
                    float v0 = acc[mi][ni][2 * half + 0] * scale;
                    float v1 = acc[mi][ni][2 * half + 1] * scale;
                    __nv_bfloat16 h0 = __float2bfloat16(v0);
                    __nv_bfloat16 h1 = __float2bfloat16(v1);
                    __nv_bfloat162 hv; hv.x = h0; hv.y = h1;
                    __nv_bfloat162 lv;
                    lv.x = __float2bfloat16(v0 - __bfloat162float(h0));
                    lv.y = __float2bfloat16(v1 - __bfloat162float(h1));
                    size_t off = (size_t)(rgl + 8 * half) * DM + cgl;
                    *(__nv_bfloat162*)&outHi[off] = hv;
                    *(__nv_bfloat162*)&outLo[off] = lv;
                }
            }
        }
    } else {
#pragma unroll
        for (int mi = 0; mi < 2; mi++) {
#pragma unroll
            for (int ni = 0; ni < 4; ni++) {
                int rgl = row0 + m0w + mi * 16 + g;
                int cgl = col0 + n0w + ni * 8 + tg * 2;
                *(float2*)&C[(size_t)rgl * DM + cgl] =
                    make_float2(acc[mi][ni][0], acc[mi][ni][1]);
                *(float2*)&C[(size_t)(rgl + 8) * DM + cgl] =
                    make_float2(acc[mi][ni][2], acc[mi][ni][3]);
            }
        }
    }
}

__global__ __launch_bounds__(512, 1)
void qkv_fused_kernel()
{
    extern __shared__ __align__(128) char smem[];
    const uint32_t sb = smem_u32(smem);
    const int z = blockIdx.z;
    const __nv_bfloat16* wh = g_w_hi + (size_t)z * DM * DM;
    const __nv_bfloat16* wl = g_w_lo + (size_t)z * DM * DM;
    __nv_bfloat16* oh = (z == 0) ? g_q_hi : (z == 1) ? g_k_hi : g_v_hi;
    __nv_bfloat16* ol = (z == 0) ? g_q_lo : (z == 1) ? g_k_lo : g_v_lo;
    float scale = (z == 0) ? 0.125f : 1.0f;
    gemm_body(g_x_hi, g_x_lo, wh, wl, nullptr, oh, ol, scale, sb,
              blockIdx.y * 128, blockIdx.x * 128);
}

__global__ __launch_bounds__(512, 1)
void oproj_kernel(float* __restrict__ out)
{
    extern __shared__ __align__(128) char smem[];
    const uint32_t sb = smem_u32(smem);
    gemm_body(g_a_hi, g_a_lo, g_w_hi + (size_t)3 * DM * DM, g_w_lo + (size_t)3 * DM * DM,
              out, nullptr, nullptr, 1.0f, sb, blockIdx.y * 128, blockIdx.x * 128);
}

// ---------------------------------------------------------------------------
// Tensor-core flash attention, 512 threads, split-key warps.
// CTA = 128 queries; iteration = 128 keys; warps 0-7 take keys [0,64),
// warps 8-15 take [64,128) with independent online softmax; merged at end.
// ---------------------------------------------------------------------------
constexpr uint32_t QT    = 128 * 144;          // 18432 per Q tensor (hi/lo)
constexpr uint32_t QREG  = 2 * QT;             // 36864
constexpr uint32_t KVT2  = 128 * 144;          // 18432 per KV tensor (128 keys)
constexpr uint32_t STG2  = 4 * KVT2;           // 73728 per stage
constexpr uint32_t ATTN_SMEM = QREG + 2 * STG2;  // 184320

__global__ __launch_bounds__(512, 1)
void attn_mma_kernel(const unsigned char* __restrict__ pad)
{
    extern __shared__ __align__(128) char dsm[];
    __shared__ float pmadd[2][128];
    __shared__ float smU_m[8][16];
    __shared__ float smU_l[8][16];
    const uint32_t sb = smem_u32(dsm);
    const int tid = threadIdx.x, lane = tid & 31, w = tid >> 5;
    const int qb = gridDim.x - 1 - blockIdx.x;   // heavy tiles first
    const int bh = blockIdx.y, b = bh >> 4, h = bh & 15;
    const int wrow = w & 7, half = w >> 3;
    const int qw0 = wrow * 16;
    const int qt0 = qb * 128;
    const int g = lane >> 2, tg = lane & 3;

    // ---- Load Q tile (hi/lo) into dedicated smem region ----
    {
        const __nv_bfloat16* qs[2] = {g_q_hi, g_q_lo};
#pragma unroll
        for (int j = 0; j < 4; j++) {
            int idx = tid + j * 512;
            int t = idx >> 10, r = (idx & 1023) >> 3, c16 = idx & 7;
            const __nv_bfloat16* src =
                qs[t] + (size_t)(b * Tt + qt0 + r) * DM + h * HD + c16 * 8;
            cp16(sb + (uint32_t)(t * (int)QT + r * 144 + c16 * 16), src);
        }
        cp_commit();
    }

    auto load_kv = [&](int kb2, int st) {
        const __nv_bfloat16* srcs[4] = {g_k_hi, g_k_lo, g_v_hi, g_v_lo};
#pragma unroll
        for (int j = 0; j < 8; j++) {
            int idx = tid + j * 512;
            int t = idx >> 10, r = (idx & 1023) >> 3, c16 = idx & 7;
            const __nv_bfloat16* src =
                srcs[t] + (size_t)(b * Tt + kb2 * 128 + r) * DM + h * HD + c16 * 8;
            cp16(sb + QREG + (uint32_t)(st * (int)STG2 + t * (int)KVT2 + r * 144 + c16 * 16), src);
        }
        if (tid < 128)
            pmadd[st][tid] = pad[b * Tt + kb2 * 128 + tid] ? -INFINITY : 0.f;
        cp_commit();
    };

    float m0 = -INFINITY, m1 = -INFINITY, l0 = 0.f, l1 = 0.f;
    float oacc[8][4];
#pragma unroll
    for (int j = 0; j < 8; j++)
#pragma unroll
        for (int cc = 0; cc < 4; cc++) oacc[j][cc] = 0.f;

    const int nkb = qb + 1;
    load_kv(0, 0);

    for (int kb = 0; kb < nkb; kb++) {
        if (kb + 1 < nkb) { load_kv(kb + 1, (kb + 1) & 1); cp_wait<1>(); }
        else              { cp_wait<0>(); }
        __syncthreads();

        const uint32_t st = sb + QREG + (uint32_t)(kb & 1) * STG2;
        const int kg0 = kb * 128 + half * 64;

        if (kg0 <= qt0 + qw0 + 15) {
            // ---- S = Q K^T ----
            float sacc[8][4];
#pragma unroll
            for (int j = 0; j < 8; j++)
#pragma unroll
                for (int cc = 0; cc < 4; cc++) sacc[j][cc] = 0.f;

            const int brow = half * 64 + (lane & 7) + ((lane >> 4) << 3);
            const uint32_t qoff0 = (uint32_t)((qw0 + (lane & 15)) * 144 + ((lane >> 4) << 4));
#pragma unroll
            for (int kt = 0; kt < 4; kt++) {
                uint32_t qh4[4], ql4[4];
                ldmat_x4(qh4, sb + qoff0 + kt * 32);
                ldmat_x4(ql4, sb + QT + qoff0 + kt * 32);

                uint32_t kh[8][2], kl[8][2];
                const int bcol = kt * 16 + (((lane >> 3) & 1) << 3);
#pragma unroll
                for (int p = 0; p < 4; p++) {
                    uint32_t off = (uint32_t)((brow + p * 16) * 144 + bcol * 2);
                    uint32_t r4[4];
                    ldmat_x4(r4, st + off);
                    kh[2 * p][0] = r4[0]; kh[2 * p][1] = r4[1];
                    kh[2 * p + 1][0] = r4[2]; kh[2 * p + 1][1] = r4[3];
                    ldmat_x4(r4, st + KVT2 + off);
                    kl[2 * p][0] = r4[0]; kl[2 * p][1] = r4[1];
                    kl[2 * p + 1][0] = r4[2]; kl[2 * p + 1][1] = r4[3];
                }
#pragma unroll
                for (int j = 0; j < 8; j++) {
                    mma_bf16(sacc[j], qh4, kh[j]);
                    mma_bf16(sacc[j], ql4, kh[j]);
                    mma_bf16(sacc[j], qh4, kl[j]);
                }
            }

            // ---- mask + padding ----
            const bool needmask = (kg0 + 63 > qt0 + qw0);
            const int qg0r = qt0 + qw0 + g;
            const int qg1r = qg0r + 8;
#pragma unroll
            for (int j = 0; j < 8; j++) {
                int lc = j * 8 + tg * 2;
                float pm0 = pmadd[kb & 1][half * 64 + lc];
                float pm1 = pmadd[kb & 1][half * 64 + lc + 1];
                sacc[j][0] += pm0; sacc[j][1] += pm1;
                sacc[j][2] += pm0; sacc[j][3] += pm1;
                if (needmask) {
                    int c0 = kg0 + lc;
                    if (c0     > qg0r) sacc[j][0] = -INFINITY;
                    if (c0 + 1 > qg0r) sacc[j][1] = -INFINITY;
                    if (c0     > qg1r) sacc[j][2] = -INFINITY;
                    if (c0 + 1 > qg1r) sacc[j][3] = -INFINITY;
                }
            }

            // ---- online softmax (per warp, its own key half) ----
            float mx0 = -INFINITY, mx1 = -INFINITY;
#pragma unroll
            for (int j = 0; j < 8; j++) {
                mx0 = fmaxf(mx0, fmaxf(sacc[j][0], sacc[j][1]));
                mx1 = fmaxf(mx1, fmaxf(sacc[j][2], sacc[j][3]));
            }
            mx0 = fmaxf(mx0, __shfl_xor_sync(0xffffffffu, mx0, 1));
            mx0 = fmaxf(mx0, __shfl_xor_sync(0xffffffffu, mx0, 2));
            mx1 = fmaxf(mx1, __shfl_xor_sync(0xffffffffu, mx1, 1));
            mx1 = fmaxf(mx1, __shfl_xor_sync(0xffffffffu, mx1, 2));

            float m0n = fmaxf(m0, mx0), m1n = fmaxf(m1, mx1);
            float a0 = __expf(m0 - m0n), a1 = __expf(m1 - m1n);

            float s0 = 0.f, s1 = 0.f;
#pragma unroll
            for (int j = 0; j < 8; j++) {
                sacc[j][0] = __expf(sacc[j][0] - m0n);
                sacc[j][1] = __expf(sacc[j][1] - m0n);
                sacc[j][2] = __expf(sacc[j][2] - m1n);
                sacc[j][3] = __expf(sacc[j][3] - m1n);
                s0 += sacc[j][0] + sacc[j][1];
                s1 += sacc[j][2] + sacc[j][3];
            }
            s0 += __shfl_xor_sync(0xffffffffu, s0, 1);
            s0 += __shfl_xor_sync(0xffffffffu, s0, 2);
            s1 += __shfl_xor_sync(0xffffffffu, s1, 1);
            s1 += __shfl_xor_sync(0xffffffffu, s1, 2);

            l0 = l0 * a0 + s0;  l1 = l1 * a1 + s1;
            m0 = m0n;  m1 = m1n;
#pragma unroll
            for (int j = 0; j < 8; j++) {
                oacc[j][0] *= a0; oacc[j][1] *= a0;
                oacc[j][2] *= a1; oacc[j][3] *= a1;
            }

            // ---- pack P into A-frags (hi/lo) ----
            uint32_t ph[4][4], pl[4][4];
#pragma unroll
            for (int kt = 0; kt < 4; kt++) {
#pragma unroll
                for (int hf = 0; hf < 2; hf++) {
                    const float* s = sacc[2 * kt + hf];
                    float f0 = s[0], f1 = s[1], f2 = s[2], f3 = s[3];
                    __nv_bfloat16 h0 = __float2bfloat16(f0);
                    __nv_bfloat16 h1 = __float2bfloat16(f1);
                    __nv_bfloat16 h2 = __float2bfloat16(f2);
                    __nv_bfloat16 h3 = __float2bfloat16(f3);
                    ph[kt][2 * hf + 0] = pack_bf2(__bfloat162float(h0), __bfloat162float(h1));
                    ph[kt][2 * hf + 1] = pack_bf2(__bfloat162float(h2), __bfloat162float(h3));
                    pl[kt][2 * hf + 0] = pack_bf2(f0 - __bfloat162float(h0),
                                                  f1 - __bfloat162float(h1));
                    pl[kt][2 * hf + 1] = pack_bf2(f2 - __bfloat162float(h2),
                                                  f3 - __bfloat162float(h3));
                }
            }

            // ---- O += P V over this warp's 64 keys ----
            const uint32_t vb = st + 2 * KVT2;   // Vhi; Vlo at +KVT2
#pragma unroll
            for (int kt = 0; kt < 4; kt++) {
                uint32_t vh[8][2], vl[8][2];
                const int vrow = half * 64 + kt * 16 + (lane & 15);
#pragma unroll
                for (int p = 0; p < 4; p++) {
                    uint32_t off = (uint32_t)(vrow * 144 + (p * 16 + ((lane >> 4) << 3)) * 2);
                    uint32_t r4[4];
                    ldmat_x4_t(r4, vb + off);
                    vh[2 * p][0] = r4[0]; vh[2 * p][1] = r4[1];
                    vh[2 * p + 1][0] = r4[2]; vh[2 * p + 1][1] = r4[3];
                    ldmat_x4_t(r4, vb + KVT2 + off);
                    vl[2 * p][0] = r4[0]; vl[2 * p][1] = r4[1];
                    vl[2 * p + 1][0] = r4[2]; vl[2 * p + 1][1] = r4[3];
                }
#pragma unroll
                for (int j = 0; j < 8; j++) {
                    mma_bf16(oacc[j], ph[kt], vh[j]);
                    mma_bf16(oacc[j], pl[kt], vh[j]);
                    mma_bf16(oacc[j], ph[kt], vl[j]);
                }
            }
        }
        __syncthreads();
    }

    // ---- split-KV merge: upper warps publish, lower warps combine ----
    if (half == 1) {
        float* cmb = (float*)(dsm) + wrow * 16 * 68;
#pragma unroll
        for (int j = 0; j < 8; j++) {
            int col = j * 8 + tg * 2;
            *(float2*)&cmb[g * 68 + col]       = make_float2(oacc[j][0], oacc[j][1]);
            *(float2*)&cmb[(g + 8) * 68 + col] = make_float2(oacc[j][2], oacc[j][3]);
        }
        if (tg == 0) {
            smU_m[wrow][g] = m0;     smU_l[wrow][g] = l0;
            smU_m[wrow][g + 8] = m1; smU_l[wrow][g + 8] = l1;
        }
    }
    __syncthreads();
    if (half == 0) {
        const float* cmb = (const float*)(dsm) + wrow * 16 * 68;
        float mb0 = smU_m[wrow][g],     lb0 = smU_l[wrow][g];
        float mb1 = smU_m[wrow][g + 8], lb1 = smU_l[wrow][g + 8];
        float M0 = fmaxf(m0, mb0), M1 = fmaxf(m1, mb1);
        float af0 = __expf(m0 - M0), bf0 = __expf(mb0 - M0);
        float af1 = __expf(m1 - M1), bf1 = __expf(mb1 - M1);
        float inv0 = 1.f / (l0 * af0 + lb0 * bf0);
        float inv1 = 1.f / (l1 * af1 + lb1 * bf1);

        const int row0 = b * Tt + qt0 + qw0 + g;
#pragma unroll
        for (int j = 0; j < 8; j++) {
            int col = j * 8 + tg * 2;
            float2 pb0 = *(const float2*)&cmb[g * 68 + col];
            float2 pb1 = *(const float2*)&cmb[(g + 8) * 68 + col];
            float o0 = (oacc[j][0] * af0 + pb0.x * bf0) * inv0;
            float o1 = (oacc[j][1] * af0 + pb0.y * bf0) * inv0;
            float o2 = (oacc[j][2] * af1 + pb1.x * bf1) * inv1;
            float o3 = (oacc[j][3] * af1 + pb1.y * bf1) * inv1;

            int gcol = h * HD + col;
            __nv_bfloat16 h0 = __float2bfloat16(o0), h1 = __float2bfloat16(o1);
            __nv_bfloat16 h2 = __float2bfloat16(o2), h3 = __float2bfloat16(o3);
            __nv_bfloat162 hv0; hv0.x = h0; hv0.y = h1;
            __nv_bfloat162 lv0;
            lv0.x = __float2bfloat16(o0 - __bfloat162float(h0));
            lv0.y = __float2bfloat16(o1 - __bfloat162float(h1));
            __nv_bfloat162 hv1; hv1.x = h2; hv1.y = h3;
            __nv_bfloat162 lv1;
            lv1.x = __float2bfloat16(o2 - __bfloat162float(h2));
            lv1.y = __float2bfloat16(o3 - __bfloat162float(h3));
            *(__nv_bfloat162*)&g_a_hi[(size_t)row0 * DM + gcol] = hv0;
            *(__nv_bfloat162*)&g_a_lo[(size_t)row0 * DM + gcol] = lv0;
            *(__nv_bfloat162*)&g_a_hi[(size_t)(row0 + 8) * DM + gcol] = hv1;
            *(__nv_bfloat162*)&g_a_lo[(size_t)(row0 + 8) * DM + gcol] = lv1;
        }
    }
}

// ---------------------------------------------------------------------------
// Launch
// ---------------------------------------------------------------------------
extern "C" void kernel_launch(void* const* d_in, const int* in_sizes, int n_in,
                              void* d_out, int out_size)
{
    const float* x  = (const float*)d_in[0];
    const unsigned char* pad = (const unsigned char*)d_in[1];
    const float* Wq = (const float*)d_in[2];
    const float* Wk = (const float*)d_in[3];
    const float* Wv = (const float*)d_in[4];
    const float* Wo = (const float*)d_in[5];
    float* out = (float*)d_out;

    void *pxh, *pxl;
    cudaGetSymbolAddress(&pxh, g_x_hi);
    cudaGetSymbolAddress(&pxl, g_x_lo);

    cudaFuncSetAttribute(qkv_fused_kernel,
                         cudaFuncAttributeMaxDynamicSharedMemorySize, GEMM_SMEM);
    cudaFuncSetAttribute(oproj_kernel,
                         cudaFuncAttributeMaxDynamicSharedMemorySize, GEMM_SMEM);
    cudaFuncSetAttribute(attn_mma_kernel,
                         cudaFuncAttributeMaxDynamicSharedMemorySize, ATTN_SMEM);

    const int NX4 = MROWS * DM / 4;
    split_kernel<<<(NX4 + 255) / 256, 256>>>(x, (__nv_bfloat16*)pxh, (__nv_bfloat16*)pxl, NX4);
    split_w_kernel<<<4 * (DM * DM / 4) / 256, 256>>>(Wq, Wk, Wv, Wo);

    dim3 gg(DM / 128, MROWS / 128, 3);
    qkv_fused_kernel<<<gg, 512, GEMM_SMEM>>>();

    dim3 attn_grid(Tt / 128, Bb * Hh);
    attn_mma_kernel<<<attn_grid, 512, ATTN_SMEM>>>(pad);

    dim3 og(DM / 128, MROWS / 128);
    oproj_kernel<<<og, 512, GEMM_SMEM>>>(out);
}

// round 10
// speedup vs baseline: 2.8658x; 1.0360x over previous
#include <cuda_runtime.h>
#include <cuda_bf16.h>
#include <cstdint>

// Problem constants
constexpr int Bb = 2;
constexpr int Tt = 2048;
constexpr int DM = 1024;
constexpr int Hh = 16;
constexpr int HD = 64;
constexpr int MROWS = Bb * Tt;   // 4096

// Scratch (no allocation allowed -> __device__ globals)
__device__ __nv_bfloat16 g_x_hi[MROWS * DM];
__device__ __nv_bfloat16 g_x_lo[MROWS * DM];
__device__ __nv_bfloat16 g_w_hi[4 * DM * DM];   // Wq, Wk, Wv, Wo
__device__ __nv_bfloat16 g_w_lo[4 * DM * DM];
__device__ __nv_bfloat16 g_q_hi[MROWS * DM];
__device__ __nv_bfloat16 g_q_lo[MROWS * DM];
__device__ __nv_bfloat16 g_k_hi[MROWS * DM];
__device__ __nv_bfloat16 g_k_lo[MROWS * DM];
__device__ __nv_bfloat16 g_v_hi[MROWS * DM];
__device__ __nv_bfloat16 g_v_lo[MROWS * DM];
__device__ __nv_bfloat16 g_a_hi[MROWS * DM];
__device__ __nv_bfloat16 g_a_lo[MROWS * DM];

// ---------------------------------------------------------------------------
// PTX helpers
// ---------------------------------------------------------------------------
__device__ __forceinline__ uint32_t smem_u32(const void* p) {
    uint32_t a;
    asm("{ .reg .u64 t; cvta.to.shared.u64 t, %1; cvt.u32.u64 %0, t; }"
        : "=r"(a) : "l"(p));
    return a;
}

__device__ __forceinline__ void ldmat_x4(uint32_t* r, uint32_t addr) {
    asm volatile("ldmatrix.sync.aligned.m8n8.x4.shared.b16 {%0,%1,%2,%3}, [%4];"
                 : "=r"(r[0]), "=r"(r[1]), "=r"(r[2]), "=r"(r[3]) : "r"(addr));
}
__device__ __forceinline__ void ldmat_x4_t(uint32_t* r, uint32_t addr) {
    asm volatile("ldmatrix.sync.aligned.m8n8.x4.trans.shared.b16 {%0,%1,%2,%3}, [%4];"
                 : "=r"(r[0]), "=r"(r[1]), "=r"(r[2]), "=r"(r[3]) : "r"(addr));
}

__device__ __forceinline__ void mma_bf16(float* c, const uint32_t* a, const uint32_t* b) {
    asm volatile(
        "mma.sync.aligned.m16n8k16.row.col.f32.bf16.bf16.f32 "
        "{%0,%1,%2,%3}, {%4,%5,%6,%7}, {%8,%9}, {%0,%1,%2,%3};"
        : "+f"(c[0]), "+f"(c[1]), "+f"(c[2]), "+f"(c[3])
        : "r"(a[0]), "r"(a[1]), "r"(a[2]), "r"(a[3]), "r"(b[0]), "r"(b[1]));
}

__device__ __forceinline__ void cp16(uint32_t dst, const void* src) {
    asm volatile("cp.async.cg.shared.global [%0], [%1], 16;" :: "r"(dst), "l"(src));
}
__device__ __forceinline__ void cp_commit() {
    asm volatile("cp.async.commit_group;");
}
template <int N> __device__ __forceinline__ void cp_wait() {
    asm volatile("cp.async.wait_group %0;" :: "n"(N));
}

__device__ __forceinline__ uint32_t pack_bf2(float lo, float hi) {
    __nv_bfloat162 v = __floats2bfloat162_rn(lo, hi);
    return *reinterpret_cast<uint32_t*>(&v);
}

// ---------------------------------------------------------------------------
// Fused split fp32 -> (hi, lo) bf16 : x AND the four weight matrices
// ---------------------------------------------------------------------------
__device__ __forceinline__ void split4(const float4 v, uint2& ho, uint2& lo2) {
    float f[4] = {v.x, v.y, v.z, v.w};
    __nv_bfloat16 h[4], l[4];
#pragma unroll
    for (int j = 0; j < 4; j++) {
        h[j] = __float2bfloat16(f[j]);
        l[j] = __float2bfloat16(f[j] - __bfloat162float(h[j]));
    }
    ho = *(uint2*)h;
    lo2 = *(uint2*)l;
}

__global__ __launch_bounds__(256) void split_all_kernel(
    const float* __restrict__ x,
    const float* __restrict__ w0, const float* __restrict__ w1,
    const float* __restrict__ w2, const float* __restrict__ w3)
{
    constexpr int NX4 = MROWS * DM / 4;   // 1,048,576
    constexpr int NW4 = DM * DM / 4;      // 262,144
    int i = blockIdx.x * blockDim.x + threadIdx.x;
    if (i < NX4) {
        uint2 h, l;
        split4(((const float4*)x)[i], h, l);
        ((uint2*)g_x_hi)[i] = h;
        ((uint2*)g_x_lo)[i] = l;
    } else {
        int j = i - NX4;                  // 0 .. 4*NW4-1
        int m = j >> 18;
        int r = j & (NW4 - 1);
        const float* src = (m == 0) ? w0 : (m == 1) ? w1 : (m == 2) ? w2 : w3;
        uint2 h, l;
        split4(((const float4*)src)[r], h, l);
        ((uint2*)g_w_hi)[(size_t)m * NW4 + r] = h;
        ((uint2*)g_w_lo)[(size_t)m * NW4 + r] = l;
    }
}

// ---------------------------------------------------------------------------
// mma.sync split-bf16 NT GEMM: CTA tile 128x64, 256 threads (8 warps, 4x2 of
// 32x32), BK=32, 3-stage cp.async pipeline, 2 CTAs per SM.
// ---------------------------------------------------------------------------
constexpr int BK = 32;
constexpr int NCH = DM / BK;                  // 32
constexpr int RS = 40;                        // row stride in bf16 elems
constexpr uint32_t TILE_A = 128 * RS * 2;     // 10240 B
constexpr uint32_t TILE_Bt = 64 * RS * 2;     // 5120 B
constexpr uint32_t STAGE_B = 2 * TILE_A + 2 * TILE_Bt;   // 30720
constexpr uint32_t GEMM_SMEM = 3 * STAGE_B;   // 92160

__device__ __forceinline__ void gemm_body(
    const __nv_bfloat16* __restrict__ Ahi,
    const __nv_bfloat16* __restrict__ Alo,
    const __nv_bfloat16* __restrict__ Bhi,
    const __nv_bfloat16* __restrict__ Blo,
    float* __restrict__ C,
    __nv_bfloat16* __restrict__ outHi,
    __nv_bfloat16* __restrict__ outLo,
    float scale, uint32_t sb, int row0, int col0)
{
    const int tid = threadIdx.x, lane = tid & 31, wid = tid >> 5;
    const int wr = wid & 3, wc = wid >> 2;       // 4x2 warp grid
    const int m0w = wr * 32, n0w = wc * 32;

    float acc[2][4][4];
#pragma unroll
    for (int mi = 0; mi < 2; mi++)
#pragma unroll
        for (int ni = 0; ni < 4; ni++)
#pragma unroll
            for (int j = 0; j < 4; j++) acc[mi][ni][j] = 0.f;

    // per chunk: A hi/lo 128x32 (1024 units) + B hi/lo 64x32 (512) = 1536 cp16
    auto load_chunk = [&](int c, int stage) {
        const int k0 = c * BK;
        const uint32_t stg = sb + (uint32_t)stage * STAGE_B;
#pragma unroll
        for (int j = 0; j < 6; j++) {
            int idx = tid + j * 256;              // 0..1535
            if (idx < 1024) {
                int t = idx >> 9, r = (idx & 511) >> 2, c16 = idx & 3;
                const __nv_bfloat16* s = (t == 0 ? Ahi : Alo);
                cp16(stg + (uint32_t)t * TILE_A + (uint32_t)(r * RS * 2 + c16 * 16),
                     s + (size_t)(row0 + r) * DM + k0 + c16 * 8);
            } else {
                int idx2 = idx - 1024;
                int t = idx2 >> 8, r = (idx2 & 255) >> 2, c16 = idx2 & 3;
                const __nv_bfloat16* s = (t == 0 ? Bhi : Blo);
                cp16(stg + 2 * TILE_A + (uint32_t)t * TILE_Bt
                         + (uint32_t)(r * RS * 2 + c16 * 16),
                     s + (size_t)(col0 + r) * DM + k0 + c16 * 8);
            }
        }
        cp_commit();
    };

    load_chunk(0, 0);
    load_chunk(1, 1);

    for (int c = 0; c < NCH; c++) {
        if (c + 2 < NCH) { load_chunk(c + 2, (c + 2) % 3); cp_wait<2>(); }
        else if (c + 1 < NCH) { cp_wait<1>(); }
        else { cp_wait<0>(); }
        __syncthreads();

        const uint32_t stg = sb + (uint32_t)(c % 3) * STAGE_B;
        const uint32_t uAh = stg, uAl = stg + TILE_A;
        const uint32_t uBh = stg + 2 * TILE_A, uBl = uBh + TILE_Bt;

        const int arow = m0w + (lane & 15);
        const int brow = n0w + (lane & 7) + ((lane >> 4) << 3);

#pragma unroll
        for (int kk = 0; kk < BK; kk += 16) {
            const int acol = kk + ((lane >> 4) << 3);
            const int bcol = kk + (((lane >> 3) & 1) << 3);
            uint32_t a_hi[2][4], a_lo[2][4], b_hi[4][2], b_lo[4][2];
#pragma unroll
            for (int mi = 0; mi < 2; mi++) {
                uint32_t off = (uint32_t)(((arow + mi * 16) * RS + acol) * 2);
                ldmat_x4(a_hi[mi], uAh + off);
                ldmat_x4(a_lo[mi], uAl + off);
            }
#pragma unroll
            for (int p = 0; p < 2; p++) {
                uint32_t off = (uint32_t)(((brow + p * 16) * RS + bcol) * 2);
                uint32_t r[4];
                ldmat_x4(r, uBh + off);
                b_hi[2 * p][0] = r[0]; b_hi[2 * p][1] = r[1];
                b_hi[2 * p + 1][0] = r[2]; b_hi[2 * p + 1][1] = r[3];
                ldmat_x4(r, uBl + off);
                b_lo[2 * p][0] = r[0]; b_lo[2 * p][1] = r[1];
                b_lo[2 * p + 1][0] = r[2]; b_lo[2 * p + 1][1] = r[3];
            }
#pragma unroll
            for (int mi = 0; mi < 2; mi++)
#pragma unroll
                for (int ni = 0; ni < 4; ni++)
                    mma_bf16(acc[mi][ni], a_hi[mi], b_hi[ni]);
#pragma unroll
            for (int mi = 0; mi < 2; mi++)
#pragma unroll
                for (int ni = 0; ni < 4; ni++)
                    mma_bf16(acc[mi][ni], a_hi[mi], b_lo[ni]);
#pragma unroll
            for (int mi = 0; mi < 2; mi++)
#pragma unroll
                for (int ni = 0; ni < 4; ni++)
                    mma_bf16(acc[mi][ni], a_lo[mi], b_hi[ni]);
        }
        __syncthreads();
    }

    const int g = lane >> 2, tg = lane & 3;
    if (outHi) {
#pragma unroll
        for (int mi = 0; mi < 2; mi++) {
#pragma unroll
            for (int ni = 0; ni < 4; ni++) {
                int rgl = row0 + m0w + mi * 16 + g;
                int cgl = col0 + n0w + ni * 8 + tg * 2;
#pragma unroll
                for (int half = 0; half < 2; half++) {
                    float v0 = acc[mi][ni][2 * half + 0] * scale;
                    float v1 = acc[mi][ni][2 * half + 1] * scale;
                    __nv_bfloat16 h0 = __float2bfloat16(v0);
                    __nv_bfloat16 h1 = __float2bfloat16(v1);
                    __nv_bfloat162 hv; hv.x = h0; hv.y = h1;
                    __nv_bfloat162 lv;
                    lv.x = __float2bfloat16(v0 - __bfloat162float(h0));
                    lv.y = __float2bfloat16(v1 - __bfloat162float(h1));
                    size_t off = (size_t)(rgl + 8 * half) * DM + cgl;
                    *(__nv_bfloat162*)&outHi[off] = hv;
                    *(__nv_bfloat162*)&outLo[off] = lv;
                }
            }
        }
    } else {
#pragma unroll
        for (int mi = 0; mi < 2; mi++) {
#pragma unroll
            for (int ni = 0; ni < 4; ni++) {
                int rgl = row0 + m0w + mi * 16 + g;
                int cgl = col0 + n0w + ni * 8 + tg * 2;
                *(float2*)&C[(size_t)rgl * DM + cgl] =
                    make_float2(acc[mi][ni][0], acc[mi][ni][1]);
                *(float2*)&C[(size_t)(rgl + 8) * DM + cgl] =
                    make_float2(acc[mi][ni][2], acc[mi][ni][3]);
            }
        }
    }
}

__global__ __launch_bounds__(256, 2)
void qkv_fused_kernel()
{
    extern __shared__ __align__(128) char smem[];
    const uint32_t sb = smem_u32(smem);
    const int z = blockIdx.z;
    const __nv_bfloat16* wh = g_w_hi + (size_t)z * DM * DM;
    const __nv_bfloat16* wl = g_w_lo + (size_t)z * DM * DM;
    __nv_bfloat16* oh = (z == 0) ? g_q_hi : (z == 1) ? g_k_hi : g_v_hi;
    __nv_bfloat16* ol = (z == 0) ? g_q_lo : (z == 1) ? g_k_lo : g_v_lo;
    float scale = (z == 0) ? 0.125f : 1.0f;
    gemm_body(g_x_hi, g_x_lo, wh, wl, nullptr, oh, ol, scale, sb,
              blockIdx.y * 128, blockIdx.x * 64);
}

__global__ __launch_bounds__(256, 2)
void oproj_kernel(float* __restrict__ out)
{
    extern __shared__ __align__(128) char smem[];
    const uint32_t sb = smem_u32(smem);
    gemm_body(g_a_hi, g_a_lo, g_w_hi + (size_t)3 * DM * DM, g_w_lo + (size_t)3 * DM * DM,
              out, nullptr, nullptr, 1.0f, sb, blockIdx.y * 128, blockIdx.x * 64);
}

// ---------------------------------------------------------------------------
// Tensor-core flash attention: 256 threads, 8 warps x 16 query rows,
// key blocks of 64, Q staged in smem (frags reloaded per k-step),
// 2 CTAs per SM. smem: Q 36864 + 2 stages x 36864 = 110592.
// ---------------------------------------------------------------------------
constexpr uint32_t QT   = 128 * 144;           // 18432 per Q tensor
constexpr uint32_t QREG = 2 * QT;              // 36864
constexpr uint32_t KVT  = 64 * 144;            // 9216 per KV tensor (64 keys)
constexpr uint32_t STG  = 4 * KVT;             // 36864 per stage
constexpr uint32_t ATTN_SMEM = QREG + 2 * STG; // 110592

__global__ __launch_bounds__(256, 2)
void attn_mma_kernel(const unsigned char* __restrict__ pad)
{
    extern __shared__ __align__(128) char dsm[];
    __shared__ float pmadd[2][64];
    const uint32_t sb = smem_u32(dsm);
    const int tid = threadIdx.x, lane = tid & 31, w = tid >> 5;
    const int qb = gridDim.x - 1 - blockIdx.x;   // heavy tiles first
    const int bh = blockIdx.y, b = bh >> 4, h = bh & 15;
    const int qw0 = w * 16;
    const int qt0 = qb * 128;
    const int g = lane >> 2, tg = lane & 3;

    // ---- Load Q tile (hi/lo) into dedicated smem region ----
    {
        const __nv_bfloat16* qs[2] = {g_q_hi, g_q_lo};
#pragma unroll
        for (int j = 0; j < 8; j++) {
            int idx = tid + j * 256;
            int t = idx >> 10, r = (idx & 1023) >> 3, c16 = idx & 7;
            const __nv_bfloat16* src =
                qs[t] + (size_t)(b * Tt + qt0 + r) * DM + h * HD + c16 * 8;
            cp16(sb + (uint32_t)(t * (int)QT + r * 144 + c16 * 16), src);
        }
        cp_commit();
    }

    auto load_kv = [&](int kb2, int st) {
        const __nv_bfloat16* srcs[4] = {g_k_hi, g_k_lo, g_v_hi, g_v_lo};
#pragma unroll
        for (int j = 0; j < 8; j++) {
            int idx = tid + j * 256;
            int t = idx >> 9, r = (idx & 511) >> 3, c16 = idx & 7;
            const __nv_bfloat16* src =
                srcs[t] + (size_t)(b * Tt + kb2 * 64 + r) * DM + h * HD + c16 * 8;
            cp16(sb + QREG + (uint32_t)(st * (int)STG + t * (int)KVT + r * 144 + c16 * 16), src);
        }
        if (tid < 64)
            pmadd[st][tid] = pad[b * Tt + kb2 * 64 + tid] ? -INFINITY : 0.f;
        cp_commit();
    };

    float m0 = -INFINITY, m1 = -INFINITY, l0 = 0.f, l1 = 0.f;
    float oacc[8][4];
#pragma unroll
    for (int j = 0; j < 8; j++)
#pragma unroll
        for (int cc = 0; cc < 4; cc++) oacc[j][cc] = 0.f;

    const int nkb = 2 * qb + 2;
    load_kv(0, 0);

    for (int kb = 0; kb < nkb; kb++) {
        if (kb + 1 < nkb) { load_kv(kb + 1, (kb + 1) & 1); cp_wait<1>(); }
        else              { cp_wait<0>(); }
        __syncthreads();

        const uint32_t st = sb + QREG + (uint32_t)(kb & 1) * STG;
        const int kg0 = kb * 64;

        if (kg0 <= qt0 + qw0 + 15) {
            // ---- S = Q K^T ----
            float sacc[8][4];
#pragma unroll
            for (int j = 0; j < 8; j++)
#pragma unroll
                for (int cc = 0; cc < 4; cc++) sacc[j][cc] = 0.f;

            const int brow = (lane & 7) + ((lane >> 4) << 3);
            const uint32_t qoff0 = (uint32_t)((qw0 + (lane & 15)) * 144 + ((lane >> 4) << 4));
#pragma unroll
            for (int kt = 0; kt < 4; kt++) {
                uint32_t qh4[4], ql4[4];
                ldmat_x4(qh4, sb + qoff0 + kt * 32);
                ldmat_x4(ql4, sb + QT + qoff0 + kt * 32);

                uint32_t kh[8][2], kl[8][2];
                const int bcol = kt * 16 + (((lane >> 3) & 1) << 3);
#pragma unroll
                for (int p = 0; p < 4; p++) {
                    uint32_t off = (uint32_t)((brow + p * 16) * 144 + bcol * 2);
                    uint32_t r4[4];
                    ldmat_x4(r4, st + off);
                    kh[2 * p][0] = r4[0]; kh[2 * p][1] = r4[1];
                    kh[2 * p + 1][0] = r4[2]; kh[2 * p + 1][1] = r4[3];
                    ldmat_x4(r4, st + KVT + off);
                    kl[2 * p][0] = r4[0]; kl[2 * p][1] = r4[1];
                    kl[2 * p + 1][0] = r4[2]; kl[2 * p + 1][1] = r4[3];
                }
#pragma unroll
                for (int j = 0; j < 8; j++) {
                    mma_bf16(sacc[j], qh4, kh[j]);
                    mma_bf16(sacc[j], ql4, kh[j]);
                    mma_bf16(sacc[j], qh4, kl[j]);
                }
            }

            // ---- mask + padding ----
            const bool needmask = (kg0 + 63 > qt0 + qw0);
            const int qg0r = qt0 + qw0 + g;
            const int qg1r = qg0r + 8;
#pragma unroll
            for (int j = 0; j < 8; j++) {
                int lc = j * 8 + tg * 2;
                float pm0 = pmadd[kb & 1][lc];
                float pm1 = pmadd[kb & 1][lc + 1];
                sacc[j][0] += pm0; sacc[j][1] += pm1;
                sacc[j][2] += pm0; sacc[j][3] += pm1;
                if (needmask) {
                    int c0 = kg0 + lc;
                    if (c0     > qg0r) sacc[j][0] = -INFINITY;
                    if (c0 + 1 > qg0r) sacc[j][1] = -INFINITY;
                    if (c0     > qg1r) sacc[j][2] = -INFINITY;
                    if (c0 + 1 > qg1r) sacc[j][3] = -INFINITY;
                }
            }

            // ---- online softmax ----
            float mx0 = -INFINITY, mx1 = -INFINITY;
#pragma unroll
            for (int j = 0; j < 8; j++) {
                mx0 = fmaxf(mx0, fmaxf(sacc[j][0], sacc[j][1]));
                mx1 = fmaxf(mx1, fmaxf(sacc[j][2], sacc[j][3]));
            }
            mx0 = fmaxf(mx0, __shfl_xor_sync(0xffffffffu, mx0, 1));
            mx0 = fmaxf(mx0, __shfl_xor_sync(0xffffffffu, mx0, 2));
            mx1 = fmaxf(mx1, __shfl_xor_sync(0xffffffffu, mx1, 1));
            mx1 = fmaxf(mx1, __shfl_xor_sync(0xffffffffu, mx1, 2));

            float m0n = fmaxf(m0, mx0), m1n = fmaxf(m1, mx1);
            float a0 = __expf(m0 - m0n), a1 = __expf(m1 - m1n);

            float s0 = 0.f, s1 = 0.f;
#pragma unroll
            for (int j = 0; j < 8; j++) {
                sacc[j][0] = __expf(sacc[j][0] - m0n);
                sacc[j][1] = __expf(sacc[j][1] - m0n);
                sacc[j][2] = __expf(sacc[j][2] - m1n);
                sacc[j][3] = __expf(sacc[j][3] - m1n);
                s0 += sacc[j][0] + sacc[j][1];
                s1 += sacc[j][2] + sacc[j][3];
            }
            s0 += __shfl_xor_sync(0xffffffffu, s0, 1);
            s0 += __shfl_xor_sync(0xffffffffu, s0, 2);
            s1 += __shfl_xor_sync(0xffffffffu, s1, 1);
            s1 += __shfl_xor_sync(0xffffffffu, s1, 2);

            l0 = l0 * a0 + s0;  l1 = l1 * a1 + s1;
            m0 = m0n;  m1 = m1n;
#pragma unroll
            for (int j = 0; j < 8; j++) {
                oacc[j][0] *= a0; oacc[j][1] *= a0;
                oacc[j][2] *= a1; oacc[j][3] *= a1;
            }

            // ---- pack P into A-frags (hi/lo) ----
            uint32_t ph[4][4], pl[4][4];
#pragma unroll
            for (int kt = 0; kt < 4; kt++) {
#pragma unroll
                for (int hf = 0; hf < 2; hf++) {
                    const float* s = sacc[2 * kt + hf];
                    float f0 = s[0], f1 = s[1], f2 = s[2], f3 = s[3];
                    __nv_bfloat16 h0 = __float2bfloat16(f0);
                    __nv_bfloat16 h1 = __float2bfloat16(f1);
                    __nv_bfloat16 h2 = __float2bfloat16(f2);
                    __nv_bfloat16 h3 = __float2bfloat16(f3);
                    ph[kt][2 * hf + 0] = pack_bf2(__bfloat162float(h0), __bfloat162float(h1));
                    ph[kt][2 * hf + 1] = pack_bf2(__bfloat162float(h2), __bfloat162float(h3));
                    pl[kt][2 * hf + 0] = pack_bf2(f0 - __bfloat162float(h0),
                                                  f1 - __bfloat162float(h1));
                    pl[kt][2 * hf + 1] = pack_bf2(f2 - __bfloat162float(h2),
                                                  f3 - __bfloat162float(h3));
                }
            }

            // ---- O += P V ----
            const uint32_t vb = st + 2 * KVT;
#pragma unroll
            for (int kt = 0; kt < 4; kt++) {
                uint32_t vh[8][2], vl[8][2];
                const int vrow = kt * 16 + (lane & 15);
#pragma unroll
                for (int p = 0; p < 4; p++) {
                    uint32_t off = (uint32_t)(vrow * 144 + (p * 16 + ((lane >> 4) << 3)) * 2);
                    uint32_t r4[4];
                    ldmat_x4_t(r4, vb + off);
                    vh[2 * p][0] = r4[0]; vh[2 * p][1] = r4[1];
                    vh[2 * p + 1][0] = r4[2]; vh[2 * p + 1][1] = r4[3];
                    ldmat_x4_t(r4, vb + KVT + off);
                    vl[2 * p][0] = r4[0]; vl[2 * p][1] = r4[1];
                    vl[2 * p + 1][0] = r4[2]; vl[2 * p + 1][1] = r4[3];
                }
#pragma unroll
                for (int j = 0; j < 8; j++) {
                    mma_bf16(oacc[j], ph[kt], vh[j]);
                    mma_bf16(oacc[j], pl[kt], vh[j]);
                    mma_bf16(oacc[j], ph[kt], vl[j]);
                }
            }
        }
        __syncthreads();
    }

    // ---- epilogue ----
    float inv0 = 1.f / l0, inv1 = 1.f / l1;
    const int row0 = b * Tt + qt0 + qw0 + g;
#pragma unroll
    for (int j = 0; j < 8; j++) {
        int col = h * HD + j * 8 + tg * 2;
        float o0 = oacc[j][0] * inv0, o1 = oacc[j][1] * inv0;
        float o2 = oacc[j][2] * inv1, o3 = oacc[j][3] * inv1;
        __nv_bfloat16 h0 = __float2bfloat16(o0), h1 = __float2bfloat16(o1);
        __nv_bfloat16 h2 = __float2bfloat16(o2), h3 = __float2bfloat16(o3);
        __nv_bfloat162 hv0; hv0.x = h0; hv0.y = h1;
        __nv_bfloat162 lv0;
        lv0.x = __float2bfloat16(o0 - __bfloat162float(h0));
        lv0.y = __float2bfloat16(o1 - __bfloat162float(h1));
        __nv_bfloat162 hv1; hv1.x = h2; hv1.y = h3;
        __nv_bfloat162 lv1;
        lv1.x = __float2bfloat16(o2 - __bfloat162float(h2));
        lv1.y = __float2bfloat16(o3 - __bfloat162float(h3));
        *(__nv_bfloat162*)&g_a_hi[(size_t)row0 * DM + col] = hv0;
        *(__nv_bfloat162*)&g_a_lo[(size_t)row0 * DM + col] = lv0;
        *(__nv_bfloat162*)&g_a_hi[(size_t)(row0 + 8) * DM + col] = hv1;
        *(__nv_bfloat162*)&g_a_lo[(size_t)(row0 + 8) * DM + col] = lv1;
    }
}

// ---------------------------------------------------------------------------
// Launch
// ---------------------------------------------------------------------------
extern "C" void kernel_launch(void* const* d_in, const int* in_sizes, int n_in,
                              void* d_out, int out_size)
{
    const float* x  = (const float*)d_in[0];
    const unsigned char* pad = (const unsigned char*)d_in[1];
    const float* Wq = (const float*)d_in[2];
    const float* Wk = (const float*)d_in[3];
    const float* Wv = (const float*)d_in[4];
    const float* Wo = (const float*)d_in[5];
    float* out = (float*)d_out;

    cudaFuncSetAttribute(qkv_fused_kernel,
                         cudaFuncAttributeMaxDynamicSharedMemorySize, GEMM_SMEM);
    cudaFuncSetAttribute(oproj_kernel,
                         cudaFuncAttributeMaxDynamicSharedMemorySize, GEMM_SMEM);
    cudaFuncSetAttribute(attn_mma_kernel,
                         cudaFuncAttributeMaxDynamicSharedMemorySize, ATTN_SMEM);

    // One fused split launch: x (1M float4) + 4 weights (1M float4)
    split_all_kernel<<<8192, 256>>>(x, Wq, Wk, Wv, Wo);

    dim3 gg(DM / 64, MROWS / 128, 3);
    qkv_fused_kernel<<<gg, 256, GEMM_SMEM>>>();

    dim3 attn_grid(Tt / 128, Bb * Hh);
    attn_mma_kernel<<<attn_grid, 256, ATTN_SMEM>>>(pad);

    dim3 og(DM / 64, MROWS / 128);
    oproj_kernel<<<og, 256, GEMM_SMEM>>>(out);
}